// round 1
// baseline (speedup 1.0000x reference)
#include <cuda_runtime.h>
#include <stdint.h>

// Problem constants
#define D 128            // node feature dim / hidden dim
#define CC 86            // output classes
#define N_EDGES_TOT 1000000
#define BM 64            // edges per block
#define NT 256           // threads per block

// Shared memory layout (float offsets)
#define OFF_AST 0        // AsT [32 kk][68]  (A slab transposed, stride 68)
#define AST_STRIDE 68
#define OFF_WS 2176      // Ws  [32 kk][132] (W1 slab, stride 132)
#define WS_STRIDE 132
#define OFF_SS 0         // Ss  [64 e][88]   (scores; overlays AsT+Ws after phase 1)
#define SS_STRIDE 88
#define OFF_HST 6400     // HsT [128 j][65]  (hidden transposed, stride 65)
#define HST_STRIDE 65
#define OFF_W2S 14720    // W2s [128 j][88] + 16 pad (over-read slack for padded cols)
#define W2S_STRIDE 88
#define SMEM_FLOATS 26000
#define SMEM_BYTES (SMEM_FLOATS * 4)

// ---------------------------------------------------------------------------
// Index dtype detection: jax may emit src/dst as int64 or (x64-disabled) int32.
// True int64 indices < 100000 have zero hi-words; int32 data reinterpreted as
// int64 has random hi-words. Checked once per launch by a prologue kernel.
// ---------------------------------------------------------------------------
__device__ int g_idx64;

__global__ void detect_idx_kernel(const unsigned long long* __restrict__ src) {
    if (blockIdx.x == 0 && threadIdx.x == 0) {
        int is64 = 1;
#pragma unroll
        for (int i = 0; i < 16; ++i)
            if ((src[i] >> 32) != 0ull) is64 = 0;
        g_idx64 = is64;
    }
}

// Packed fp32x2 FMA (B300: FFMA-3reg issues at half rate; f32x2 restores peak)
__device__ __forceinline__ void fmax2(unsigned long long& acc,
                                      unsigned long long a,
                                      unsigned long long b) {
    asm("fma.rn.f32x2 %0, %1, %2, %0;" : "+l"(acc) : "l"(a), "l"(b));
}
__device__ __forceinline__ unsigned long long dup2(float x) {
    unsigned long long r;
    asm("mov.b64 %0, {%1, %1};" : "=l"(r) : "f"(x));
    return r;
}

__global__ __launch_bounds__(NT, 2)
void mlp_edge_kernel(const float* __restrict__ h,
                     const float* __restrict__ W1,
                     const float* __restrict__ b1,
                     const float* __restrict__ W2,
                     const float* __restrict__ b2,
                     const void* __restrict__ srcp,
                     const void* __restrict__ dstp,
                     float* __restrict__ out)
{
    extern __shared__ float sm[];
    __shared__ int rs[BM];
    __shared__ int rd[BM];

    const int t = threadIdx.x;
    const long long e0 = (long long)blockIdx.x * BM;
    const int tm = t >> 4;   // 0..15 -> edges tm*4 .. tm*4+3
    const int tn = t & 15;   // 0..15 -> cols  tn*8 .. tn*8+7 (phase 1)

    // Load edge indices for this tile
    {
        const int is64 = g_idx64;
        if (t < BM) {
            rs[t] = is64 ? (int)((const long long*)srcp)[e0 + t]
                         : ((const int*)srcp)[e0 + t];
        } else if (t < 2 * BM) {
            const int i = t - BM;
            rd[i] = is64 ? (int)((const long long*)dstp)[e0 + i]
                         : ((const int*)dstp)[e0 + i];
        }
    }

    // Stage W2 [128][86] -> [128][88] once (sync provided by first slab barrier)
    for (int idx = t; idx < D * CC; idx += NT) {
        const int r = idx / CC;
        const int c = idx - r * CC;
        sm[OFF_W2S + r * W2S_STRIDE + c] = W2[idx];
    }

    // ---------------- Phase 1: hid = relu([h_u | h_v] @ W1 + b1) -----------
    unsigned long long acc[4][4];
#pragma unroll
    for (int i = 0; i < 4; ++i)
#pragma unroll
        for (int p = 0; p < 4; ++p) acc[i][p] = 0ull;

    for (int s = 0; s < 8; ++s) {   // 8 k-slabs of 32 over K=256
        __syncthreads();
        // Stage W1 slab [32][128] -> Ws
        {
            const float4* w1p = (const float4*)(W1 + s * 32 * D);
#pragma unroll
            for (int r = 0; r < 4; ++r) {
                const int idx4 = t + r * NT;          // 0..1023
                const int kk = idx4 >> 5;             // row within slab
                const int j4 = (idx4 & 31) << 2;      // col (float units)
                const float4 v = __ldg(&w1p[idx4]);
                *(float4*)&sm[OFF_WS + kk * WS_STRIDE + j4] = v;
            }
        }
        // Stage gathered A slab (transposed): AsT[kk][e]
        {
            const int* rows = (s < 4) ? rs : rd;
            const int kc = (s & 3) * 32;
#pragma unroll
            for (int r = 0; r < 2; ++r) {
                const int g = t + r * NT;             // 0..511
                const int e = g >> 3;
                const int q = g & 7;
                const float4* hp =
                    (const float4*)(h + (long long)rows[e] * D + kc) + q;
                const float4 v = __ldg(hp);
                float* d2 = &sm[OFF_AST + (q * 4) * AST_STRIDE + e];
                d2[0 * AST_STRIDE] = v.x;
                d2[1 * AST_STRIDE] = v.y;
                d2[2 * AST_STRIDE] = v.z;
                d2[3 * AST_STRIDE] = v.w;
            }
        }
        __syncthreads();
        // Compute 32 k-steps: 16 f32x2 FMA per step per thread
#pragma unroll 4
        for (int kk = 0; kk < 32; ++kk) {
            const float4 av = *(const float4*)&sm[OFF_AST + kk * AST_STRIDE + tm * 4];
            const ulonglong2* bp =
                (const ulonglong2*)&sm[OFF_WS + kk * WS_STRIDE + tn * 8];
            const ulonglong2 b01 = bp[0];
            const ulonglong2 b23 = bp[1];
            const unsigned long long a0 = dup2(av.x);
            const unsigned long long a1 = dup2(av.y);
            const unsigned long long a2 = dup2(av.z);
            const unsigned long long a3 = dup2(av.w);
            fmax2(acc[0][0], a0, b01.x); fmax2(acc[0][1], a0, b01.y);
            fmax2(acc[0][2], a0, b23.x); fmax2(acc[0][3], a0, b23.y);
            fmax2(acc[1][0], a1, b01.x); fmax2(acc[1][1], a1, b01.y);
            fmax2(acc[1][2], a1, b23.x); fmax2(acc[1][3], a1, b23.y);
            fmax2(acc[2][0], a2, b01.x); fmax2(acc[2][1], a2, b01.y);
            fmax2(acc[2][2], a2, b23.x); fmax2(acc[2][3], a2, b23.y);
            fmax2(acc[3][0], a3, b01.x); fmax2(acc[3][1], a3, b01.y);
            fmax2(acc[3][2], a3, b23.x); fmax2(acc[3][3], a3, b23.y);
        }
    }

    // Epilogue 1: + b1, ReLU, store hidden transposed HsT[j][e]
#pragma unroll
    for (int p = 0; p < 4; ++p) {
        const int j = tn * 8 + p * 2;
        const float bl = __ldg(&b1[j]);
        const float bh = __ldg(&b1[j + 1]);
#pragma unroll
        for (int i = 0; i < 4; ++i) {
            const float2 v = *(float2*)&acc[i][p];
            float x = v.x + bl; x = x > 0.f ? x : 0.f;
            float y = v.y + bh; y = y > 0.f ? y : 0.f;
            const int e = tm * 4 + i;
            sm[OFF_HST + j * HST_STRIDE + e] = x;
            sm[OFF_HST + (j + 1) * HST_STRIDE + e] = y;
        }
    }
    __syncthreads();

    // ---------------- Phase 2: score = hid @ W2 + b2 -----------------------
    unsigned long long acc2[4][3];
#pragma unroll
    for (int i = 0; i < 4; ++i)
#pragma unroll
        for (int p = 0; p < 3; ++p) acc2[i][p] = 0ull;

    const int cb = tn * 6;   // cols cb..cb+5 (cols >= 86 computed, discarded)
#pragma unroll 4
    for (int j = 0; j < D; ++j) {
        const unsigned long long* bp =
            (const unsigned long long*)&sm[OFF_W2S + j * W2S_STRIDE + cb];
        const unsigned long long b0 = bp[0];
        const unsigned long long b1v = bp[1];
        const unsigned long long b2v = bp[2];
        const float* ap = &sm[OFF_HST + j * HST_STRIDE + tm * 4];
        const unsigned long long a0 = dup2(ap[0]);
        const unsigned long long a1 = dup2(ap[1]);
        const unsigned long long a2 = dup2(ap[2]);
        const unsigned long long a3 = dup2(ap[3]);
        fmax2(acc2[0][0], a0, b0); fmax2(acc2[0][1], a0, b1v); fmax2(acc2[0][2], a0, b2v);
        fmax2(acc2[1][0], a1, b0); fmax2(acc2[1][1], a1, b1v); fmax2(acc2[1][2], a1, b2v);
        fmax2(acc2[2][0], a2, b0); fmax2(acc2[2][1], a2, b1v); fmax2(acc2[2][2], a2, b2v);
        fmax2(acc2[3][0], a3, b0); fmax2(acc2[3][1], a3, b1v); fmax2(acc2[3][2], a3, b2v);
    }

    // Epilogue 2: + b2, stage into Ss (overlays AsT/Ws, safe post-barrier)
#pragma unroll
    for (int p = 0; p < 3; ++p) {
        const int c = cb + p * 2;
        const float bl = __ldg(&b2[c < CC ? c : CC - 1]);
        const float bh = __ldg(&b2[(c + 1) < CC ? (c + 1) : CC - 1]);
#pragma unroll
        for (int i = 0; i < 4; ++i) {
            const float2 v = *(float2*)&acc2[i][p];
            const int e = tm * 4 + i;
            if (c < CC)     sm[OFF_SS + e * SS_STRIDE + c]     = v.x + bl;
            if (c + 1 < CC) sm[OFF_SS + e * SS_STRIDE + c + 1] = v.y + bh;
        }
    }
    __syncthreads();

    // Coalesced write-out: 64 edges x 86 classes, contiguous per tile
    float* op = out + e0 * CC;
    for (int idx = t; idx < BM * CC; idx += NT) {
        const int e = idx / CC;
        const int c = idx - e * CC;
        op[idx] = sm[OFF_SS + e * SS_STRIDE + c];
    }
}

extern "C" void kernel_launch(void* const* d_in, const int* in_sizes, int n_in,
                              void* d_out, int out_size) {
    const float* h  = (const float*)d_in[0];
    const float* W1 = (const float*)d_in[1];
    const float* b1 = (const float*)d_in[2];
    const float* W2 = (const float*)d_in[3];
    const float* b2 = (const float*)d_in[4];
    const void* src = d_in[5];
    const void* dst = d_in[6];
    float* out = (float*)d_out;
    (void)in_sizes; (void)n_in; (void)out_size;

    cudaFuncSetAttribute(mlp_edge_kernel,
                         cudaFuncAttributeMaxDynamicSharedMemorySize, SMEM_BYTES);

    detect_idx_kernel<<<1, 32>>>((const unsigned long long*)src);
    mlp_edge_kernel<<<N_EDGES_TOT / BM, NT, SMEM_BYTES>>>(
        h, W1, b1, W2, b2, src, dst, out);
}

// round 4
// speedup vs baseline: 3.0502x; 3.0502x over previous
#include <cuda_runtime.h>
#include <cuda_bf16.h>
#include <stdint.h>

#define NE      1000000
#define DD      128
#define CC      86
#define BM      128
#define NT      256
#define NTILES  ((NE + BM - 1) / BM)   // 7813

// ---------------- smem layout (bytes) ----------------
// Double-buffered staging: BUF(i) 64KB each: AH|AL|WH|WL (16KB each)
#define BUF(i)   ((i) * 65536)
#define OFF_AH   0
#define OFF_AL   16384
#define OFF_WH   32768
#define OFF_WL   49152
// Overlays after layer1:
#define SM_W2H   0            // in buf0: 24KB (2 slabs x 12288)
#define SM_W2L   24576        // in buf0: 24KB
#define SM_HIDH  65536        // in buf1: 32KB (2 slabs x 16384)
#define SM_HIDL  98304        // in buf1: 32KB
#define SM_SC    0            // scores f32 [128][96] = 48KB (post-layer2, buf0)
// misc tail
#define SM_B1    131072       // 128 f32
#define SM_B2    131584       // 96 f32
#define SM_RS    131968       // 128 int
#define SM_RD    132480       // 128 int
#define SMEM_BYTES 133120

#define SWZ(x) ((x) ^ ((((uint32_t)(x)) >> 3) & 0x70))

// ---------------- ptx helpers ----------------
__device__ __forceinline__ uint32_t smem_u32(const void* p) {
    uint32_t a;
    asm("{ .reg .u64 t; cvta.to.shared.u64 t, %1; cvt.u32.u64 %0, t; }" : "=r"(a) : "l"(p));
    return a;
}
#define CP16(dst, src) \
    asm volatile("cp.async.cg.shared.global [%0], [%1], 16;" :: "r"(dst), "l"(src))
#define CP_COMMIT() asm volatile("cp.async.commit_group;" ::: "memory")
#define CP_WAIT(n)  asm volatile("cp.async.wait_group %0;" :: "n"(n) : "memory")

__device__ __forceinline__ void ldsm4(uint32_t r[4], uint32_t addr) {
    asm volatile("ldmatrix.sync.aligned.m8n8.x4.shared.b16 {%0,%1,%2,%3}, [%4];"
                 : "=r"(r[0]), "=r"(r[1]), "=r"(r[2]), "=r"(r[3]) : "r"(addr));
}
__device__ __forceinline__ void mma16816(float c[4], const uint32_t a[4],
                                         uint32_t b0, uint32_t b1) {
    asm volatile("mma.sync.aligned.m16n8k16.row.col.f32.bf16.bf16.f32 "
                 "{%0,%1,%2,%3}, {%4,%5,%6,%7}, {%8,%9}, {%0,%1,%2,%3};"
                 : "+f"(c[0]), "+f"(c[1]), "+f"(c[2]), "+f"(c[3])
                 : "r"(a[0]), "r"(a[1]), "r"(a[2]), "r"(a[3]), "r"(b0), "r"(b1));
}
__device__ __forceinline__ uint32_t pack2(float even, float odd) {
    uint32_t r;   // upper16 = odd, lower16 = even  -> memory order [even][odd]
    asm("cvt.rn.satfinite.bf16x2.f32 %0, %1, %2;" : "=r"(r) : "f"(odd), "f"(even));
    return r;
}
__device__ __forceinline__ float bflo(uint32_t w) { return __uint_as_float(w << 16); }
__device__ __forceinline__ float bfhi(uint32_t w) { return __uint_as_float(w & 0xffff0000u); }

// ---------------- global scratch ----------------
__device__ __align__(128) unsigned char g_hh[NE / 1000 * 100 * 0 + 100000 * 256]; // h hi bf16 [node][128]
__device__ __align__(128) unsigned char g_hl[100000 * 256];                       // h lo bf16
__device__ __align__(128) unsigned char g_w1t[2][65536];  // [hi/lo][4 slabs x [128n][64k] SW]
__device__ __align__(128) unsigned char g_w2t[2][24576];  // [hi/lo][2 slabs x [96n][64k]  SW]
__device__ int g_idx64;

__global__ void detect_idx_kernel(const unsigned long long* __restrict__ src) {
    if (threadIdx.x == 0) {
        int is64 = 1;
#pragma unroll
        for (int i = 0; i < 16; ++i)
            if ((src[i] >> 32) != 0ull) is64 = 0;
        g_idx64 = is64;
    }
}

__global__ void prep_w_kernel(const float* __restrict__ W1, const float* __restrict__ W2) {
    int i = blockIdx.x * blockDim.x + threadIdx.x;
    if (i < 128 * 256) {                     // W1T: n=0..127, k=0..255
        int n = i >> 8, k = i & 255;
        float w = W1[k * DD + n];
        __nv_bfloat16 hb = __float2bfloat16(w);
        __nv_bfloat16 lb = __float2bfloat16(w - __bfloat162float(hb));
        int slab = k >> 6, kk = k & 63;
        uint32_t off = slab * 16384 + SWZ(n * 128 + kk * 2);
        *(__nv_bfloat16*)(g_w1t[0] + off) = hb;
        *(__nv_bfloat16*)(g_w1t[1] + off) = lb;
    } else if (i < 128 * 256 + 96 * 128) {   // W2T: n=0..95 (pad zero), k=0..127
        int j = i - 128 * 256;
        int n = j >> 7, k = j & 127;
        float w = (n < CC) ? W2[k * CC + n] : 0.0f;
        __nv_bfloat16 hb = __float2bfloat16(w);
        __nv_bfloat16 lb = __float2bfloat16(w - __bfloat162float(hb));
        int slab = k >> 6, kk = k & 63;
        uint32_t off = slab * 12288 + SWZ(n * 128 + kk * 2);
        *(__nv_bfloat16*)(g_w2t[0] + off) = hb;
        *(__nv_bfloat16*)(g_w2t[1] + off) = lb;
    }
}

__global__ void prep_h_kernel(const float* __restrict__ h) {
    int i = blockIdx.x * blockDim.x + threadIdx.x;   // over 100000*128
    if (i < 100000 * 128) {
        float v = h[i];
        __nv_bfloat16 hb = __float2bfloat16(v);
        __nv_bfloat16 lb = __float2bfloat16(v - __bfloat162float(hb));
        *(__nv_bfloat16*)(g_hh + (size_t)i * 2) = hb;
        *(__nv_bfloat16*)(g_hl + (size_t)i * 2) = lb;
    }
}

// ---------------- staging ----------------
__device__ __forceinline__ void issue_slab(char* sm8, uint32_t smb, int s, int buf,
                                           const int* rows, int t) {
    const int koff2 = (s & 1) * 128;          // byte offset within 256B node row
    const uint32_t AHb = smb + BUF(buf) + OFF_AH;
    const uint32_t ALb = smb + BUF(buf) + OFF_AL;
    const uint32_t WHb = smb + BUF(buf) + OFF_WH;
    const uint32_t WLb = smb + BUF(buf) + OFF_WL;
#pragma unroll
    for (int r = 0; r < 4; ++r) {
        const int g = r * NT + t;             // 0..1023 16B chunks
        const int e = g >> 3, q = g & 7;
        const size_t nb = (size_t)rows[e] * 256 + koff2 + q * 16;
        const uint32_t off = SWZ(e * 128 + q * 16);
        CP16(AHb + off, (const char*)g_hh + nb);
        CP16(ALb + off, (const char*)g_hl + nb);
        CP16(WHb + g * 16, (const char*)g_w1t[0] + s * 16384 + g * 16);
        CP16(WLb + g * 16, (const char*)g_w1t[1] + s * 16384 + g * 16);
    }
}

// ---------------- main fused kernel ----------------
__global__ __launch_bounds__(NT, 1)
void mlp_mma_kernel(const float* __restrict__ b1g,
                    const float* __restrict__ b2g,
                    const void* __restrict__ srcp,
                    const void* __restrict__ dstp,
                    float* __restrict__ out)
{
    extern __shared__ char sm8[];
    const uint32_t smb = smem_u32(sm8);
    const int t = threadIdx.x;
    const int lane = t & 31;
    const int w = t >> 5;
    const int warp_m = w & 3;        // 32-row slice
    const int warp_n = w >> 2;       // layer1: 64-col slice; layer2: 48-col slice
    const long long e0 = (long long)blockIdx.x * BM;
    const int is64 = g_idx64;

    float* b1s = (float*)(sm8 + SM_B1);
    float* b2s = (float*)(sm8 + SM_B2);
    int* rs = (int*)(sm8 + SM_RS);
    int* rd = (int*)(sm8 + SM_RD);

    if (t < 128) {
        b1s[t] = b1g[t];
        long long e = e0 + t;
        int vs = 0, vd = 0;
        if (e < NE) {
            if (is64) { vs = (int)((const long long*)srcp)[e]; vd = (int)((const long long*)dstp)[e]; }
            else      { vs = ((const int*)srcp)[e];            vd = ((const int*)dstp)[e]; }
        }
        rs[t] = vs; rd[t] = vd;
    } else if (t < 224) {
        const int c = t - 128;
        b2s[c] = (c < CC) ? b2g[c] : 0.0f;
    }
    __syncthreads();

    // ===================== Layer 1 =====================
    float acc[2][8][4];
#pragma unroll
    for (int mt = 0; mt < 2; ++mt)
#pragma unroll
        for (int nt = 0; nt < 8; ++nt)
#pragma unroll
            for (int q = 0; q < 4; ++q) acc[mt][nt][q] = 0.0f;

    issue_slab(sm8, smb, 0, 0, rs, t);
    CP_COMMIT();

    for (int s = 0; s < 4; ++s) {
        __syncthreads();                       // prev compute done before reusing buf
        if (s < 3) {
            issue_slab(sm8, smb, s + 1, (s + 1) & 1, (s + 1 < 2) ? rs : rd, t);
            CP_COMMIT();
        } else {
            // stage W2 (both slabs, hi+lo) into buf0 (free now)
            const uint32_t W2Hb = smb + SM_W2H;
            const uint32_t W2Lb = smb + SM_W2L;
#pragma unroll
            for (int r = 0; r < 6; ++r) {
                const int g = r * NT + t;      // 0..1535
                CP16(W2Hb + g * 16, (const char*)g_w2t[0] + g * 16);
                CP16(W2Lb + g * 16, (const char*)g_w2t[1] + g * 16);
            }
            CP_COMMIT();
        }
        CP_WAIT(1);                            // slab s landed
        __syncthreads();

        const uint32_t AHb = smb + BUF(s & 1) + OFF_AH;
        const uint32_t ALb = smb + BUF(s & 1) + OFF_AL;
        const uint32_t WHb = smb + BUF(s & 1) + OFF_WH;
        const uint32_t WLb = smb + BUF(s & 1) + OFF_WL;
#pragma unroll
        for (int p = 0; p < 3; ++p) {          // HH, HL, LH
            const uint32_t ab = (p == 2) ? ALb : AHb;
            const uint32_t bb = (p == 1) ? WLb : WHb;
#pragma unroll
            for (int ks = 0; ks < 4; ++ks) {
                const int k0 = ks * 16;
                uint32_t a[2][4];
#pragma unroll
                for (int mt = 0; mt < 2; ++mt) {
                    const int row = warp_m * 32 + mt * 16 + (lane & 15);
                    const int col = k0 + (lane >> 4) * 8;
                    ldsm4(a[mt], ab + SWZ(row * 128 + col * 2));
                }
#pragma unroll
                for (int nt2 = 0; nt2 < 4; ++nt2) {
                    uint32_t b[4];
                    const int row = warp_n * 64 + nt2 * 16 + (lane & 7) + ((lane & 16) ? 8 : 0);
                    const int col = k0 + ((lane & 8) ? 8 : 0);
                    ldsm4(b, bb + SWZ(row * 128 + col * 2));
                    mma16816(acc[0][nt2 * 2 + 0], a[0], b[0], b[1]);
                    mma16816(acc[0][nt2 * 2 + 1], a[0], b[2], b[3]);
                    mma16816(acc[1][nt2 * 2 + 0], a[1], b[0], b[1]);
                    mma16816(acc[1][nt2 * 2 + 1], a[1], b[2], b[3]);
                }
            }
        }
    }

    __syncthreads();   // all layer1 reads of buf1 done before hid overlays it

    // ===================== Epilogue 1: bias+relu -> hid hi/lo =====================
    {
        char* hh = sm8 + SM_HIDH + warp_n * 16384;   // k-slab = warp_n
        char* hl = sm8 + SM_HIDL + warp_n * 16384;
#pragma unroll
        for (int mt = 0; mt < 2; ++mt) {
#pragma unroll
            for (int nt = 0; nt < 8; ++nt) {
                float* c = acc[mt][nt];
                const int n = warp_n * 64 + nt * 8 + 2 * (lane & 3);
                const float bl_ = b1s[n], bh_ = b1s[n + 1];
                float v00 = c[0] + bl_; v00 = v00 > 0.f ? v00 : 0.f;
                float v01 = c[1] + bh_; v01 = v01 > 0.f ? v01 : 0.f;
                float v10 = c[2] + bl_; v10 = v10 > 0.f ? v10 : 0.f;
                float v11 = c[3] + bh_; v11 = v11 > 0.f ? v11 : 0.f;
                const uint32_t h0 = pack2(v00, v01);
                const uint32_t h1 = pack2(v10, v11);
                const uint32_t l0 = pack2(v00 - bflo(h0), v01 - bfhi(h0));
                const uint32_t l1 = pack2(v10 - bflo(h1), v11 - bfhi(h1));
                const int kk = nt * 8 + 2 * (lane & 3);
                const int row0 = warp_m * 32 + mt * 16 + (lane >> 2);
                const uint32_t oA = SWZ(row0 * 128 + kk * 2);
                const uint32_t oB = SWZ((row0 + 8) * 128 + kk * 2);
                *(uint32_t*)(hh + oA) = h0;  *(uint32_t*)(hl + oA) = l0;
                *(uint32_t*)(hh + oB) = h1;  *(uint32_t*)(hl + oB) = l1;
            }
        }
    }
    CP_WAIT(0);        // W2 landed
    __syncthreads();   // hid + W2 visible to all

    // ===================== Layer 2 =====================
    float acc2[2][6][4];
#pragma unroll
    for (int mt = 0; mt < 2; ++mt)
#pragma unroll
        for (int nt = 0; nt < 6; ++nt)
#pragma unroll
            for (int q = 0; q < 4; ++q) acc2[mt][nt][q] = 0.0f;

#pragma unroll
    for (int p = 0; p < 3; ++p) {
        const uint32_t abase = smb + ((p == 2) ? SM_HIDL : SM_HIDH);
        const uint32_t bbase = smb + ((p == 1) ? SM_W2L : SM_W2H);
#pragma unroll
        for (int ks = 0; ks < 8; ++ks) {
            const int kslab = ks >> 2;
            const int k0 = (ks & 3) * 16;
            const uint32_t ab = abase + kslab * 16384;
            const uint32_t bb = bbase + kslab * 12288;
            uint32_t a[2][4];
#pragma unroll
            for (int mt = 0; mt < 2; ++mt) {
                const int row = warp_m * 32 + mt * 16 + (lane & 15);
                const int col = k0 + (lane >> 4) * 8;
                ldsm4(a[mt], ab + SWZ(row * 128 + col * 2));
            }
#pragma unroll
            for (int nt2 = 0; nt2 < 3; ++nt2) {
                uint32_t b[4];
                const int row = warp_n * 48 + nt2 * 16 + (lane & 7) + ((lane & 16) ? 8 : 0);
                const int col = k0 + ((lane & 8) ? 8 : 0);
                ldsm4(b, bb + SWZ(row * 128 + col * 2));
                mma16816(acc2[0][nt2 * 2 + 0], a[0], b[0], b[1]);
                mma16816(acc2[0][nt2 * 2 + 1], a[0], b[2], b[3]);
                mma16816(acc2[1][nt2 * 2 + 0], a[1], b[0], b[1]);
                mma16816(acc2[1][nt2 * 2 + 1], a[1], b[2], b[3]);
            }
        }
    }

    __syncthreads();   // all W2 reads done before scores overlay buf0

    // ===================== Epilogue 2: bias -> smem -> coalesced out =====================
    {
        float* sc = (float*)(sm8 + SM_SC);
#pragma unroll
        for (int mt = 0; mt < 2; ++mt) {
#pragma unroll
            for (int nt = 0; nt < 6; ++nt) {
                float* c = acc2[mt][nt];
                const int n = warp_n * 48 + nt * 8 + 2 * (lane & 3);
                const float bl_ = b2s[n], bh_ = b2s[n + 1];
                const int row0 = warp_m * 32 + mt * 16 + (lane >> 2);
                *(float2*)(sc + row0 * 96 + n)       = make_float2(c[0] + bl_, c[1] + bh_);
                *(float2*)(sc + (row0 + 8) * 96 + n) = make_float2(c[2] + bl_, c[3] + bh_);
            }
        }
        __syncthreads();
        for (int idx = t; idx < BM * CC; idx += NT) {
            const int row = idx / CC;
            const int col = idx - row * CC;
            if (e0 + row < NE)
                out[(e0 + row) * CC + col] = sc[row * 96 + col];
        }
    }
}

extern "C" void kernel_launch(void* const* d_in, const int* in_sizes, int n_in,
                              void* d_out, int out_size) {
    const float* h  = (const float*)d_in[0];
    const float* W1 = (const float*)d_in[1];
    const float* b1 = (const float*)d_in[2];
    const float* W2 = (const float*)d_in[3];
    const float* b2 = (const float*)d_in[4];
    const void* src = d_in[5];
    const void* dst = d_in[6];
    float* out = (float*)d_out;
    (void)in_sizes; (void)n_in; (void)out_size;

    cudaFuncSetAttribute(mlp_mma_kernel,
                         cudaFuncAttributeMaxDynamicSharedMemorySize, SMEM_BYTES);

    detect_idx_kernel<<<1, 32>>>((const unsigned long long*)src);
    prep_w_kernel<<<(128 * 256 + 96 * 128 + 255) / 256, 256>>>(W1, W2);
    prep_h_kernel<<<(100000 * 128 + 255) / 256, 256>>>(h);
    mlp_mma_kernel<<<NTILES, NT, SMEM_BYTES>>>(b1, b2, src, dst, out);
}

// round 6
// speedup vs baseline: 3.2611x; 1.0691x over previous
#include <cuda_runtime.h>
#include <cuda_bf16.h>
#include <stdint.h>

#define NE      1000000
#define DD      128
#define CC      86
#define BM      128
#define NT      512
#define NTILES  ((NE + BM - 1) / BM)   // 7813

// ---------------- smem layout (bytes) ----------------
#define BUF(i)   ((i) * 65536)
#define OFF_AH   0
#define OFF_AL   16384
#define OFF_WH   32768
#define OFF_WL   49152
// Overlays after layer1:
#define SM_W2H   0            // buf0: 24KB (2 slabs x 12288)
#define SM_W2L   24576        // buf0: 24KB
#define SM_HIDH  65536        // buf1: 32KB (2 slabs x 16384)
#define SM_HIDL  98304        // buf1: 32KB
// misc tail
#define SM_B1    131072       // 128 f32
#define SM_B2    131584       // 96 f32
#define SM_RS    131968       // 128 int
#define SM_RD    132480       // 128 int
#define SMEM_BYTES 133120

#define SWZ(x) ((x) ^ ((((uint32_t)(x)) >> 3) & 0x70))

// ---------------- ptx helpers ----------------
__device__ __forceinline__ uint32_t smem_u32(const void* p) {
    uint32_t a;
    asm("{ .reg .u64 t; cvta.to.shared.u64 t, %1; cvt.u32.u64 %0, t; }" : "=r"(a) : "l"(p));
    return a;
}
#define CP16(dst, src) \
    asm volatile("cp.async.cg.shared.global [%0], [%1], 16;" :: "r"(dst), "l"(src))
#define CP_COMMIT() asm volatile("cp.async.commit_group;" ::: "memory")
#define CP_WAIT(n)  asm volatile("cp.async.wait_group %0;" :: "n"(n) : "memory")

__device__ __forceinline__ void ldsm4(uint32_t r[4], uint32_t addr) {
    asm volatile("ldmatrix.sync.aligned.m8n8.x4.shared.b16 {%0,%1,%2,%3}, [%4];"
                 : "=r"(r[0]), "=r"(r[1]), "=r"(r[2]), "=r"(r[3]) : "r"(addr));
}
__device__ __forceinline__ void ldsm2(uint32_t r[2], uint32_t addr) {
    asm volatile("ldmatrix.sync.aligned.m8n8.x2.shared.b16 {%0,%1}, [%2];"
                 : "=r"(r[0]), "=r"(r[1]) : "r"(addr));
}
__device__ __forceinline__ void mma16816(float c[4], const uint32_t a[4],
                                         uint32_t b0, uint32_t b1) {
    asm volatile("mma.sync.aligned.m16n8k16.row.col.f32.bf16.bf16.f32 "
                 "{%0,%1,%2,%3}, {%4,%5,%6,%7}, {%8,%9}, {%0,%1,%2,%3};"
                 : "+f"(c[0]), "+f"(c[1]), "+f"(c[2]), "+f"(c[3])
                 : "r"(a[0]), "r"(a[1]), "r"(a[2]), "r"(a[3]), "r"(b0), "r"(b1));
}
__device__ __forceinline__ uint32_t pack2(float even, float odd) {
    uint32_t r;   // upper16 = odd, lower16 = even  -> memory order [even][odd]
    asm("cvt.rn.satfinite.bf16x2.f32 %0, %1, %2;" : "=r"(r) : "f"(odd), "f"(even));
    return r;
}
__device__ __forceinline__ float bflo(uint32_t w) { return __uint_as_float(w << 16); }
__device__ __forceinline__ float bfhi(uint32_t w) { return __uint_as_float(w & 0xffff0000u); }

// ---------------- global scratch ----------------
__device__ __align__(128) unsigned char g_hh[100000 * 256];   // h hi bf16 [node][128]
__device__ __align__(128) unsigned char g_hl[100000 * 256];   // h lo bf16
__device__ __align__(128) unsigned char g_w1t[2][65536];      // [hi/lo][4 slabs x [128n][64k] SW]
__device__ __align__(128) unsigned char g_w2t[2][24576];      // [hi/lo][2 slabs x [96n][64k]  SW]
__device__ int g_idx64;

__global__ void detect_idx_kernel(const unsigned long long* __restrict__ src) {
    if (threadIdx.x == 0) {
        int is64 = 1;
#pragma unroll
        for (int i = 0; i < 16; ++i)
            if ((src[i] >> 32) != 0ull) is64 = 0;
        g_idx64 = is64;
    }
}

__global__ void prep_w_kernel(const float* __restrict__ W1, const float* __restrict__ W2) {
    int i = blockIdx.x * blockDim.x + threadIdx.x;
    if (i < 128 * 256) {                     // W1T: n=0..127, k=0..255
        int n = i >> 8, k = i & 255;
        float w = W1[k * DD + n];
        __nv_bfloat16 hb = __float2bfloat16(w);
        __nv_bfloat16 lb = __float2bfloat16(w - __bfloat162float(hb));
        int slab = k >> 6, kk = k & 63;
        uint32_t off = slab * 16384 + SWZ(n * 128 + kk * 2);
        *(__nv_bfloat16*)(g_w1t[0] + off) = hb;
        *(__nv_bfloat16*)(g_w1t[1] + off) = lb;
    } else if (i < 128 * 256 + 96 * 128) {   // W2T: n=0..95 (pad zero), k=0..127
        int j = i - 128 * 256;
        int n = j >> 7, k = j & 127;
        float w = (n < CC) ? W2[k * CC + n] : 0.0f;
        __nv_bfloat16 hb = __float2bfloat16(w);
        __nv_bfloat16 lb = __float2bfloat16(w - __bfloat162float(hb));
        int slab = k >> 6, kk = k & 63;
        uint32_t off = slab * 12288 + SWZ(n * 128 + kk * 2);
        *(__nv_bfloat16*)(g_w2t[0] + off) = hb;
        *(__nv_bfloat16*)(g_w2t[1] + off) = lb;
    }
}

__global__ void prep_h_kernel(const float* __restrict__ h) {
    int i = blockIdx.x * blockDim.x + threadIdx.x;   // over 100000*128
    if (i < 100000 * 128) {
        float v = h[i];
        __nv_bfloat16 hb = __float2bfloat16(v);
        __nv_bfloat16 lb = __float2bfloat16(v - __bfloat162float(hb));
        *(__nv_bfloat16*)(g_hh + (size_t)i * 2) = hb;
        *(__nv_bfloat16*)(g_hl + (size_t)i * 2) = lb;
    }
}

// ---------------- staging ----------------
__device__ __forceinline__ void issue_slab(uint32_t smb, int s, int buf,
                                           const int* rows, int t) {
    const int koff2 = (s & 1) * 128;          // byte offset within 256B node row
    const uint32_t AHb = smb + BUF(buf) + OFF_AH;
    const uint32_t ALb = smb + BUF(buf) + OFF_AL;
    const uint32_t WHb = smb + BUF(buf) + OFF_WH;
    const uint32_t WLb = smb + BUF(buf) + OFF_WL;
#pragma unroll
    for (int r = 0; r < 2; ++r) {
        const int g = r * NT + t;             // 0..1023 16B chunks
        const int e = g >> 3, q = g & 7;
        const size_t nb = (size_t)rows[e] * 256 + koff2 + q * 16;
        const uint32_t off = SWZ(e * 128 + q * 16);
        CP16(AHb + off, (const char*)g_hh + nb);
        CP16(ALb + off, (const char*)g_hl + nb);
        CP16(WHb + g * 16, (const char*)g_w1t[0] + s * 16384 + g * 16);
        CP16(WLb + g * 16, (const char*)g_w1t[1] + s * 16384 + g * 16);
    }
}

// ---------------- main fused kernel ----------------
__global__ __launch_bounds__(NT, 1)
void mlp_mma_kernel(const float* __restrict__ b1g,
                    const float* __restrict__ b2g,
                    const void* __restrict__ srcp,
                    const void* __restrict__ dstp,
                    float* __restrict__ out)
{
    extern __shared__ char sm8[];
    const uint32_t smb = smem_u32(sm8);
    const int t = threadIdx.x;
    const int lane = t & 31;
    const int w = t >> 5;            // 0..15
    const int warp_m = w & 3;        // 32-row slice
    const int warp_n = w >> 2;       // layer1: 32-col slice; layer2: 24-col slice
    const long long e0 = (long long)blockIdx.x * BM;
    const int is64 = g_idx64;

    float* b1s = (float*)(sm8 + SM_B1);
    float* b2s = (float*)(sm8 + SM_B2);
    int* rs = (int*)(sm8 + SM_RS);
    int* rd = (int*)(sm8 + SM_RD);

    if (t < 128) {
        b1s[t] = b1g[t];
        long long e = e0 + t;
        int vs = 0, vd = 0;
        if (e < NE) {
            if (is64) { vs = (int)((const long long*)srcp)[e]; vd = (int)((const long long*)dstp)[e]; }
            else      { vs = ((const int*)srcp)[e];            vd = ((const int*)dstp)[e]; }
        }
        rs[t] = vs; rd[t] = vd;
    } else if (t < 224) {
        const int c = t - 128;
        b2s[c] = (c < CC) ? b2g[c] : 0.0f;
    }
    __syncthreads();

    // ===================== Layer 1 =====================
    float acc[2][4][4];
#pragma unroll
    for (int mt = 0; mt < 2; ++mt)
#pragma unroll
        for (int nt = 0; nt < 4; ++nt)
#pragma unroll
            for (int q = 0; q < 4; ++q) acc[mt][nt][q] = 0.0f;

    issue_slab(smb, 0, 0, rs, t);
    CP_COMMIT();

    for (int s = 0; s < 4; ++s) {
        __syncthreads();                       // prev compute done before reusing buf
        if (s < 3) {
            issue_slab(smb, s + 1, (s + 1) & 1, (s + 1 < 2) ? rs : rd, t);
            CP_COMMIT();
        } else {
            // stage W2 (both slabs, hi+lo) into buf0 (free now)
            const uint32_t W2Hb = smb + SM_W2H;
            const uint32_t W2Lb = smb + SM_W2L;
#pragma unroll
            for (int r = 0; r < 3; ++r) {
                const int g = r * NT + t;      // 0..1535
                CP16(W2Hb + g * 16, (const char*)g_w2t[0] + g * 16);
                CP16(W2Lb + g * 16, (const char*)g_w2t[1] + g * 16);
            }
            CP_COMMIT();
        }
        CP_WAIT(1);                            // slab s landed
        __syncthreads();

        const uint32_t AHb = smb + BUF(s & 1) + OFF_AH;
        const uint32_t ALb = smb + BUF(s & 1) + OFF_AL;
        const uint32_t WHb = smb + BUF(s & 1) + OFF_WH;
        const uint32_t WLb = smb + BUF(s & 1) + OFF_WL;
#pragma unroll
        for (int p = 0; p < 3; ++p) {          // HH, HL, LH
            const uint32_t ab = (p == 2) ? ALb : AHb;
            const uint32_t bb = (p == 1) ? WLb : WHb;
#pragma unroll
            for (int ks = 0; ks < 4; ++ks) {
                const int k0 = ks * 16;
                uint32_t a[2][4];
#pragma unroll
                for (int mt = 0; mt < 2; ++mt) {
                    const int row = warp_m * 32 + mt * 16 + (lane & 15);
                    const int col = k0 + (lane >> 4) * 8;
                    ldsm4(a[mt], ab + SWZ(row * 128 + col * 2));
                }
                // 32 cols of B = 2 x ldsm4 (16 n-rows each)
#pragma unroll
                for (int nh = 0; nh < 2; ++nh) {
                    uint32_t b[4];
                    const int row = warp_n * 32 + nh * 16 + (lane & 7) + ((lane & 16) ? 8 : 0);
                    const int col = k0 + ((lane & 8) ? 8 : 0);
                    ldsm4(b, bb + SWZ(row * 128 + col * 2));
                    mma16816(acc[0][nh * 2 + 0], a[0], b[0], b[1]);
                    mma16816(acc[0][nh * 2 + 1], a[0], b[2], b[3]);
                    mma16816(acc[1][nh * 2 + 0], a[1], b[0], b[1]);
                    mma16816(acc[1][nh * 2 + 1], a[1], b[2], b[3]);
                }
            }
        }
    }

    __syncthreads();   // all layer1 reads of buf1 done before hid overlays it

    // ===================== Epilogue 1: bias+relu -> hid hi/lo =====================
    {
        const int slab = warp_n >> 1;                 // cols 0..63 -> slab0, 64..127 -> slab1
        char* hh = sm8 + SM_HIDH + slab * 16384;
        char* hl = sm8 + SM_HIDL + slab * 16384;
#pragma unroll
        for (int mt = 0; mt < 2; ++mt) {
#pragma unroll
            for (int nt = 0; nt < 4; ++nt) {
                float* c = acc[mt][nt];
                const int n = warp_n * 32 + nt * 8 + 2 * (lane & 3);
                const float bl_ = b1s[n], bh_ = b1s[n + 1];
                float v00 = c[0] + bl_; v00 = v00 > 0.f ? v00 : 0.f;
                float v01 = c[1] + bh_; v01 = v01 > 0.f ? v01 : 0.f;
                float v10 = c[2] + bl_; v10 = v10 > 0.f ? v10 : 0.f;
                float v11 = c[3] + bh_; v11 = v11 > 0.f ? v11 : 0.f;
                const uint32_t h0 = pack2(v00, v01);
                const uint32_t h1 = pack2(v10, v11);
                const uint32_t l0 = pack2(v00 - bflo(h0), v01 - bfhi(h0));
                const uint32_t l1 = pack2(v10 - bflo(h1), v11 - bfhi(h1));
                const int kk = (warp_n & 1) * 32 + nt * 8 + 2 * (lane & 3);  // 0..63 within slab
                const int row0 = warp_m * 32 + mt * 16 + (lane >> 2);
                const uint32_t oA = SWZ(row0 * 128 + kk * 2);
                const uint32_t oB = SWZ((row0 + 8) * 128 + kk * 2);
                *(uint32_t*)(hh + oA) = h0;  *(uint32_t*)(hl + oA) = l0;
                *(uint32_t*)(hh + oB) = h1;  *(uint32_t*)(hl + oB) = l1;
            }
        }
    }
    CP_WAIT(0);        // W2 landed
    __syncthreads();   // hid + W2 visible to all

    // ===================== Layer 2 =====================
    float acc2[2][3][4];
#pragma unroll
    for (int mt = 0; mt < 2; ++mt)
#pragma unroll
        for (int nt = 0; nt < 3; ++nt)
#pragma unroll
            for (int q = 0; q < 4; ++q) acc2[mt][nt][q] = 0.0f;

#pragma unroll
    for (int p = 0; p < 3; ++p) {
        const uint32_t abase = smb + ((p == 2) ? SM_HIDL : SM_HIDH);
        const uint32_t bbase = smb + ((p == 1) ? SM_W2L : SM_W2H);
#pragma unroll
        for (int ks = 0; ks < 8; ++ks) {
            const int kslab = ks >> 2;
            const int k0 = (ks & 3) * 16;
            const uint32_t ab = abase + kslab * 16384;
            const uint32_t bb = bbase + kslab * 12288;
            uint32_t a[2][4];
#pragma unroll
            for (int mt = 0; mt < 2; ++mt) {
                const int row = warp_m * 32 + mt * 16 + (lane & 15);
                const int col = k0 + (lane >> 4) * 8;
                ldsm4(a[mt], ab + SWZ(row * 128 + col * 2));
            }
#pragma unroll
            for (int nt2 = 0; nt2 < 3; ++nt2) {
                uint32_t b[2];
                const int row = warp_n * 24 + nt2 * 8 + (lane & 7);
                const int col = k0 + ((lane & 8) ? 8 : 0);
                ldsm2(b, bb + SWZ(row * 128 + col * 2));
                mma16816(acc2[0][nt2], a[0], b[0], b[1]);
                mma16816(acc2[1][nt2], a[1], b[0], b[1]);
            }
        }
    }

    // ===================== Epilogue 2: bias -> direct gmem stores =====================
    {
#pragma unroll
        for (int mt = 0; mt < 2; ++mt) {
#pragma unroll
            for (int nt2 = 0; nt2 < 3; ++nt2) {
                float* c = acc2[mt][nt2];
                const int n = warp_n * 24 + nt2 * 8 + 2 * (lane & 3);
                if (n < CC) {
                    const float bl_ = b2s[n], bh_ = b2s[n + 1];
                    const int row0 = warp_m * 32 + mt * 16 + (lane >> 2);
                    const long long eA = e0 + row0;
                    const long long eB = eA + 8;
                    if (eA < NE)
                        *(float2*)(out + eA * CC + n) = make_float2(c[0] + bl_, c[1] + bh_);
                    if (eB < NE)
                        *(float2*)(out + eB * CC + n) = make_float2(c[2] + bl_, c[3] + bh_);
                }
            }
        }
    }
}

extern "C" void kernel_launch(void* const* d_in, const int* in_sizes, int n_in,
                              void* d_out, int out_size) {
    const float* h  = (const float*)d_in[0];
    const float* W1 = (const float*)d_in[1];
    const float* b1 = (const float*)d_in[2];
    const float* W2 = (const float*)d_in[3];
    const float* b2 = (const float*)d_in[4];
    const void* src = d_in[5];
    const void* dst = d_in[6];
    float* out = (float*)d_out;
    (void)in_sizes; (void)n_in; (void)out_size;

    cudaFuncSetAttribute(mlp_mma_kernel,
                         cudaFuncAttributeMaxDynamicSharedMemorySize, SMEM_BYTES);

    detect_idx_kernel<<<1, 32>>>((const unsigned long long*)src);
    prep_w_kernel<<<(128 * 256 + 96 * 128 + 255) / 256, 256>>>(W1, W2);
    prep_h_kernel<<<(100000 * 128 + 255) / 256, 256>>>(h);
    mlp_mma_kernel<<<NTILES, NT, SMEM_BYTES>>>(b1, b2, src, dst, out);
}

// round 8
// speedup vs baseline: 3.8535x; 1.1816x over previous
#include <cuda_runtime.h>
#include <cuda_bf16.h>
#include <stdint.h>

#define NE      1000000
#define DD      128
#define CC      86
#define BM      64
#define NT      256
#define NTILES  ((NE + BM - 1) / BM)   // 15625

// ---------------- smem layout (bytes) ----------------
// Two 48KB buffers: AH(8K) | AL(8K) | WH(16K) | WL(16K)
#define BUF(i)   ((i) * 49152)
#define OFF_AH   0
#define OFF_AL   8192
#define OFF_WH   16384
#define OFF_WL   32768
// Phase-2 overlays:
#define SM_HIDH  0            // buf0: 16KB (2 slabs x 8192: [64e][64k] bf16 SW)
#define SM_HIDL  16384        // buf0: 16KB
#define SM_W2H   49152        // buf1: 24KB (2 slabs x 12288: [96n][64k])
#define SM_W2L   (49152 + 24576)
// tail
#define SM_RS    98304        // 64 int
#define SM_RD    98560        // 64 int
#define SMEM_BYTES 98816

#define SWZ(x) ((x) ^ ((((uint32_t)(x)) >> 3) & 0x70))

// ---------------- ptx helpers ----------------
__device__ __forceinline__ uint32_t smem_u32(const void* p) {
    uint32_t a;
    asm("{ .reg .u64 t; cvta.to.shared.u64 t, %1; cvt.u32.u64 %0, t; }" : "=r"(a) : "l"(p));
    return a;
}
#define CP16(dst, src) \
    asm volatile("cp.async.cg.shared.global [%0], [%1], 16;" :: "r"(dst), "l"(src))
#define CP_COMMIT() asm volatile("cp.async.commit_group;" ::: "memory")
#define CP_WAIT(n)  asm volatile("cp.async.wait_group %0;" :: "n"(n) : "memory")

__device__ __forceinline__ void ldsm4(uint32_t r[4], uint32_t addr) {
    asm volatile("ldmatrix.sync.aligned.m8n8.x4.shared.b16 {%0,%1,%2,%3}, [%4];"
                 : "=r"(r[0]), "=r"(r[1]), "=r"(r[2]), "=r"(r[3]) : "r"(addr));
}
__device__ __forceinline__ void ldsm2(uint32_t r[2], uint32_t addr) {
    asm volatile("ldmatrix.sync.aligned.m8n8.x2.shared.b16 {%0,%1}, [%2];"
                 : "=r"(r[0]), "=r"(r[1]) : "r"(addr));
}
__device__ __forceinline__ void mma16816(float c[4], const uint32_t a[4],
                                         uint32_t b0, uint32_t b1) {
    asm volatile("mma.sync.aligned.m16n8k16.row.col.f32.bf16.bf16.f32 "
                 "{%0,%1,%2,%3}, {%4,%5,%6,%7}, {%8,%9}, {%0,%1,%2,%3};"
                 : "+f"(c[0]), "+f"(c[1]), "+f"(c[2]), "+f"(c[3])
                 : "r"(a[0]), "r"(a[1]), "r"(a[2]), "r"(a[3]), "r"(b0), "r"(b1));
}
__device__ __forceinline__ uint32_t pack2(float even, float odd) {
    uint32_t r;   // upper16 = odd, lower16 = even -> memory order [even][odd]
    asm("cvt.rn.satfinite.bf16x2.f32 %0, %1, %2;" : "=r"(r) : "f"(odd), "f"(even));
    return r;
}
__device__ __forceinline__ float bflo(uint32_t w) { return __uint_as_float(w << 16); }
__device__ __forceinline__ float bfhi(uint32_t w) { return __uint_as_float(w & 0xffff0000u); }

// ---------------- global scratch ----------------
__device__ __align__(128) unsigned char g_hh[100000 * 256];   // h hi bf16 [node][128]
__device__ __align__(128) unsigned char g_hl[100000 * 256];   // h lo bf16
__device__ __align__(128) unsigned char g_w1t[2][65536];      // [hi/lo][4 slabs x [128n][64k] SW]
__device__ __align__(128) unsigned char g_w2t[2][24576];      // [hi/lo][2 slabs x [96n][64k]  SW]
__device__ int g_idx64;

__global__ void detect_idx_kernel(const unsigned long long* __restrict__ src) {
    if (threadIdx.x == 0) {
        int is64 = 1;
#pragma unroll
        for (int i = 0; i < 16; ++i)
            if ((src[i] >> 32) != 0ull) is64 = 0;
        g_idx64 = is64;
    }
}

__global__ void prep_w_kernel(const float* __restrict__ W1, const float* __restrict__ W2) {
    int i = blockIdx.x * blockDim.x + threadIdx.x;
    if (i < 128 * 256) {                     // W1T: n=0..127, k=0..255
        int n = i >> 8, k = i & 255;
        float w = W1[k * DD + n];
        __nv_bfloat16 hb = __float2bfloat16(w);
        __nv_bfloat16 lb = __float2bfloat16(w - __bfloat162float(hb));
        int slab = k >> 6, kk = k & 63;
        uint32_t off = slab * 16384 + SWZ(n * 128 + kk * 2);
        *(__nv_bfloat16*)(g_w1t[0] + off) = hb;
        *(__nv_bfloat16*)(g_w1t[1] + off) = lb;
    } else if (i < 128 * 256 + 96 * 128) {   // W2T: n=0..95 (pad zero), k=0..127
        int j = i - 128 * 256;
        int n = j >> 7, k = j & 127;
        float w = (n < CC) ? W2[k * CC + n] : 0.0f;
        __nv_bfloat16 hb = __float2bfloat16(w);
        __nv_bfloat16 lb = __float2bfloat16(w - __bfloat162float(hb));
        int slab = k >> 6, kk = k & 63;
        uint32_t off = slab * 12288 + SWZ(n * 128 + kk * 2);
        *(__nv_bfloat16*)(g_w2t[0] + off) = hb;
        *(__nv_bfloat16*)(g_w2t[1] + off) = lb;
    }
}

__global__ void prep_h_kernel(const float* __restrict__ h) {
    int i = blockIdx.x * blockDim.x + threadIdx.x;   // over 100000*128
    if (i < 100000 * 128) {
        float v = h[i];
        __nv_bfloat16 hb = __float2bfloat16(v);
        __nv_bfloat16 lb = __float2bfloat16(v - __bfloat162float(hb));
        *(__nv_bfloat16*)(g_hh + (size_t)i * 2) = hb;
        *(__nv_bfloat16*)(g_hl + (size_t)i * 2) = lb;
    }
}

// ---------------- staging: one K-slab (64 wide) of A(hi/lo) + W1(hi/lo) ----
__device__ __forceinline__ void issue_slab(uint32_t smb, int s, int buf,
                                           const int* rows, int t) {
    const int koff2 = (s & 1) * 128;          // byte offset within 256B node row
    const uint32_t AHb = smb + BUF(buf) + OFF_AH;
    const uint32_t ALb = smb + BUF(buf) + OFF_AL;
    const uint32_t WHb = smb + BUF(buf) + OFF_WH;
    const uint32_t WLb = smb + BUF(buf) + OFF_WL;
#pragma unroll
    for (int r = 0; r < 2; ++r) {
        const int g = r * NT + t;             // 0..511 16B chunks
        const int e = g >> 3, q = g & 7;
        const size_t nb = (size_t)rows[e] * 256 + koff2 + q * 16;
        const uint32_t off = SWZ(e * 128 + q * 16);
        CP16(AHb + off, (const char*)g_hh + nb);
        CP16(ALb + off, (const char*)g_hl + nb);
    }
#pragma unroll
    for (int r = 0; r < 4; ++r) {
        const int g = r * NT + t;             // 0..1023 16B chunks
        CP16(WHb + g * 16, (const char*)g_w1t[0] + s * 16384 + g * 16);
        CP16(WLb + g * 16, (const char*)g_w1t[1] + s * 16384 + g * 16);
    }
}

// ---------------- main fused kernel ----------------
__global__ __launch_bounds__(NT, 2)
void mlp_mma_kernel(const float* __restrict__ b1g,
                    const float* __restrict__ b2g,
                    const void* __restrict__ srcp,
                    const void* __restrict__ dstp,
                    float* __restrict__ out)
{
    extern __shared__ char sm8[];
    const uint32_t smb = smem_u32(sm8);
    const int t = threadIdx.x;
    const int lane = t & 31;
    const int w = t >> 5;            // 0..7
    const int warp_m = w & 1;        // 32-row slice
    const int warp_n = w >> 1;       // layer1: 32-col slice; layer2: 24-col slice
    const long long e0 = (long long)blockIdx.x * BM;
    const int is64 = g_idx64;

    int* rs = (int*)(sm8 + SM_RS);
    int* rd = (int*)(sm8 + SM_RD);

    if (t < BM) {
        long long e = e0 + t;
        if (is64) { rs[t] = (int)((const long long*)srcp)[e]; rd[t] = (int)((const long long*)dstp)[e]; }
        else      { rs[t] = ((const int*)srcp)[e];            rd[t] = ((const int*)dstp)[e]; }
    }
    __syncthreads();

    // ===================== Layer 1 =====================
    float acc[2][4][4];
#pragma unroll
    for (int mt = 0; mt < 2; ++mt)
#pragma unroll
        for (int nt = 0; nt < 4; ++nt)
#pragma unroll
            for (int q = 0; q < 4; ++q) acc[mt][nt][q] = 0.0f;

    issue_slab(smb, 0, 0, rs, t);
    CP_COMMIT();

    for (int s = 0; s < 4; ++s) {
        __syncthreads();                       // buf(s+1)&1 free (compute s-1 done)
        if (s < 3) {
            issue_slab(smb, s + 1, (s + 1) & 1, (s + 1 < 2) ? rs : rd, t);
            CP_COMMIT();
            CP_WAIT(1);                        // slab s landed
        } else {
            CP_WAIT(0);
        }
        __syncthreads();

        const uint32_t AHb = smb + BUF(s & 1) + OFF_AH;
        const uint32_t ALb = smb + BUF(s & 1) + OFF_AL;
        const uint32_t WHb = smb + BUF(s & 1) + OFF_WH;
        const uint32_t WLb = smb + BUF(s & 1) + OFF_WL;
#pragma unroll
        for (int p = 0; p < 3; ++p) {          // HH, HL, LH
            const uint32_t ab = (p == 2) ? ALb : AHb;
            const uint32_t bb = (p == 1) ? WLb : WHb;
#pragma unroll
            for (int ks = 0; ks < 4; ++ks) {
                const int k0 = ks * 16;
                uint32_t a[2][4];
#pragma unroll
                for (int mt = 0; mt < 2; ++mt) {
                    const int row = warp_m * 32 + mt * 16 + (lane & 15);
                    const int col = k0 + (lane >> 4) * 8;
                    ldsm4(a[mt], ab + SWZ(row * 128 + col * 2));
                }
#pragma unroll
                for (int nh = 0; nh < 2; ++nh) {
                    uint32_t b[4];
                    const int row = warp_n * 32 + nh * 16 + (lane & 7) + ((lane & 16) ? 8 : 0);
                    const int col = k0 + ((lane & 8) ? 8 : 0);
                    ldsm4(b, bb + SWZ(row * 128 + col * 2));
                    mma16816(acc[0][nh * 2 + 0], a[0], b[0], b[1]);
                    mma16816(acc[0][nh * 2 + 1], a[0], b[2], b[3]);
                    mma16816(acc[1][nh * 2 + 0], a[1], b[0], b[1]);
                    mma16816(acc[1][nh * 2 + 1], a[1], b[2], b[3]);
                }
            }
        }
    }

    __syncthreads();   // slab3 reads of buf1 done before W2 overwrites it

    // --- stage W2 (both slabs, hi+lo) into buf1; overlaps epilogue below ---
    {
        const uint32_t W2Hb = smb + SM_W2H;
        const uint32_t W2Lb = smb + SM_W2L;
#pragma unroll
        for (int r = 0; r < 6; ++r) {
            const int g = r * NT + t;          // 0..1535
            CP16(W2Hb + g * 16, (const char*)g_w2t[0] + g * 16);
            CP16(W2Lb + g * 16, (const char*)g_w2t[1] + g * 16);
        }
        CP_COMMIT();
    }

    // ===================== Epilogue 1: bias+relu -> hid hi/lo (buf0) ========
    {
        const int slab = warp_n >> 1;                 // cols 0..63 -> slab0; 64..127 -> slab1
        char* hh = sm8 + SM_HIDH + slab * 8192;
        char* hl = sm8 + SM_HIDL + slab * 8192;
#pragma unroll
        for (int mt = 0; mt < 2; ++mt) {
#pragma unroll
            for (int nt = 0; nt < 4; ++nt) {
                float* c = acc[mt][nt];
                const int n = warp_n * 32 + nt * 8 + 2 * (lane & 3);
                const float bl_ = __ldg(&b1g[n]), bh_ = __ldg(&b1g[n + 1]);
                float v00 = c[0] + bl_; v00 = v00 > 0.f ? v00 : 0.f;
                float v01 = c[1] + bh_; v01 = v01 > 0.f ? v01 : 0.f;
                float v10 = c[2] + bl_; v10 = v10 > 0.f ? v10 : 0.f;
                float v11 = c[3] + bh_; v11 = v11 > 0.f ? v11 : 0.f;
                const uint32_t h0 = pack2(v00, v01);
                const uint32_t h1 = pack2(v10, v11);
                const uint32_t l0 = pack2(v00 - bflo(h0), v01 - bfhi(h0));
                const uint32_t l1 = pack2(v10 - bflo(h1), v11 - bfhi(h1));
                const int kk = (warp_n & 1) * 32 + nt * 8 + 2 * (lane & 3);  // 0..63 in slab
                const int row0 = warp_m * 32 + mt * 16 + (lane >> 2);
                const uint32_t oA = SWZ(row0 * 128 + kk * 2);
                const uint32_t oB = SWZ((row0 + 8) * 128 + kk * 2);
                *(uint32_t*)(hh + oA) = h0;  *(uint32_t*)(hl + oA) = l0;
                *(uint32_t*)(hh + oB) = h1;  *(uint32_t*)(hl + oB) = l1;
            }
        }
    }
    CP_WAIT(0);        // W2 landed
    __syncthreads();   // hid + W2 visible to all

    // ===================== Layer 2 =====================
    float acc2[2][3][4];
#pragma unroll
    for (int mt = 0; mt < 2; ++mt)
#pragma unroll
        for (int nt = 0; nt < 3; ++nt)
#pragma unroll
            for (int q = 0; q < 4; ++q) acc2[mt][nt][q] = 0.0f;

#pragma unroll
    for (int p = 0; p < 3; ++p) {
        const uint32_t abase = smb + ((p == 2) ? SM_HIDL : SM_HIDH);
        const uint32_t bbase = smb + ((p == 1) ? SM_W2L : SM_W2H);
#pragma unroll
        for (int ks = 0; ks < 8; ++ks) {
            const int kslab = ks >> 2;
            const int k0 = (ks & 3) * 16;
            const uint32_t ab = abase + kslab * 8192;
            const uint32_t bb = bbase + kslab * 12288;
            uint32_t a[2][4];
#pragma unroll
            for (int mt = 0; mt < 2; ++mt) {
                const int row = warp_m * 32 + mt * 16 + (lane & 15);
                const int col = k0 + (lane >> 4) * 8;
                ldsm4(a[mt], ab + SWZ(row * 128 + col * 2));
            }
#pragma unroll
            for (int nt2 = 0; nt2 < 3; ++nt2) {
                uint32_t b[2];
                const int row = warp_n * 24 + nt2 * 8 + (lane & 7);
                const int col = k0 + ((lane & 8) ? 8 : 0);
                ldsm2(b, bb + SWZ(row * 128 + col * 2));
                mma16816(acc2[0][nt2], a[0], b[0], b[1]);
                mma16816(acc2[1][nt2], a[1], b[0], b[1]);
            }
        }
    }

    // ===================== Epilogue 2: bias -> direct gmem stores ===========
    {
#pragma unroll
        for (int mt = 0; mt < 2; ++mt) {
#pragma unroll
            for (int nt2 = 0; nt2 < 3; ++nt2) {
                float* c = acc2[mt][nt2];
                const int n = warp_n * 24 + nt2 * 8 + 2 * (lane & 3);
                if (n < CC) {      // n even, so (n, n+1) both < 86 when n <= 84
                    const float bl_ = __ldg(&b2g[n]), bh_ = __ldg(&b2g[n + 1]);
                    const int row0 = warp_m * 32 + mt * 16 + (lane >> 2);
                    const long long eA = e0 + row0;
                    *(float2*)(out + eA * CC + n)       = make_float2(c[0] + bl_, c[1] + bh_);
                    *(float2*)(out + (eA + 8) * CC + n) = make_float2(c[2] + bl_, c[3] + bh_);
                }
            }
        }
    }
}

extern "C" void kernel_launch(void* const* d_in, const int* in_sizes, int n_in,
                              void* d_out, int out_size) {
    const float* h  = (const float*)d_in[0];
    const float* W1 = (const float*)d_in[1];
    const float* b1 = (const float*)d_in[2];
    const float* W2 = (const float*)d_in[3];
    const float* b2 = (const float*)d_in[4];
    const void* src = d_in[5];
    const void* dst = d_in[6];
    float* out = (float*)d_out;
    (void)in_sizes; (void)n_in; (void)out_size;

    cudaFuncSetAttribute(mlp_mma_kernel,
                         cudaFuncAttributeMaxDynamicSharedMemorySize, SMEM_BYTES);

    detect_idx_kernel<<<1, 32>>>((const unsigned long long*)src);
    prep_w_kernel<<<(128 * 256 + 96 * 128 + 255) / 256, 256>>>(W1, W2);
    prep_h_kernel<<<(100000 * 128 + 255) / 256, 256>>>(h);
    mlp_mma_kernel<<<NTILES, NT, SMEM_BYTES>>>(b1, b2, src, dst, out);
}

// round 9
// speedup vs baseline: 5.8961x; 1.5301x over previous
#include <cuda_runtime.h>
#include <cuda_fp16.h>
#include <stdint.h>

#define NE      1000000
#define DD      128
#define CC      86
#define BM      64
#define NT      256
#define NTILES  ((NE + BM - 1) / BM)   // 15625

// ---------------- smem layout (bytes) ----------------
// Three 32KB buffers: AH(8K) | AL(8K) | W(16K)
#define BUF(i)   ((i) * 32768)
#define OFF_AH   0
#define OFF_AL   8192
#define OFF_W    16384
// Phase-2 overlays:
#define SM_W2    32768        // buf1: 24KB single fp16 (2 slabs x 12288)
#define SM_HIDH  65536        // buf2: 16KB (2 slabs x 8192: [64e][64k] fp16 SW)
#define SM_HIDL  81920        // buf2: 16KB
// tail
#define SM_RS    98304        // 64 int
#define SM_RD    98560        // 64 int
#define SMEM_BYTES 98816

#define SWZ(x) ((x) ^ ((((uint32_t)(x)) >> 3) & 0x70))

// ---------------- ptx helpers ----------------
__device__ __forceinline__ uint32_t smem_u32(const void* p) {
    uint32_t a;
    asm("{ .reg .u64 t; cvta.to.shared.u64 t, %1; cvt.u32.u64 %0, t; }" : "=r"(a) : "l"(p));
    return a;
}
#define CP16(dst, src) \
    asm volatile("cp.async.cg.shared.global [%0], [%1], 16;" :: "r"(dst), "l"(src))
#define CP_COMMIT() asm volatile("cp.async.commit_group;" ::: "memory")
#define CP_WAIT(n)  asm volatile("cp.async.wait_group %0;" :: "n"(n) : "memory")

__device__ __forceinline__ void ldsm4(uint32_t r[4], uint32_t addr) {
    asm volatile("ldmatrix.sync.aligned.m8n8.x4.shared.b16 {%0,%1,%2,%3}, [%4];"
                 : "=r"(r[0]), "=r"(r[1]), "=r"(r[2]), "=r"(r[3]) : "r"(addr));
}
__device__ __forceinline__ void ldsm2(uint32_t r[2], uint32_t addr) {
    asm volatile("ldmatrix.sync.aligned.m8n8.x2.shared.b16 {%0,%1}, [%2];"
                 : "=r"(r[0]), "=r"(r[1]) : "r"(addr));
}
__device__ __forceinline__ void mma16816(float c[4], const uint32_t a[4],
                                         uint32_t b0, uint32_t b1) {
    asm volatile("mma.sync.aligned.m16n8k16.row.col.f32.f16.f16.f32 "
                 "{%0,%1,%2,%3}, {%4,%5,%6,%7}, {%8,%9}, {%0,%1,%2,%3};"
                 : "+f"(c[0]), "+f"(c[1]), "+f"(c[2]), "+f"(c[3])
                 : "r"(a[0]), "r"(a[1]), "r"(a[2]), "r"(a[3]), "r"(b0), "r"(b1));
}
// Split (x,y) into fp16 hi pair (packed, x in low half) + fp16 lo-residual pair
__device__ __forceinline__ uint32_t packsplit(float x, float y, uint32_t& lo) {
    const __half hx = __float2half_rn(x), hy = __float2half_rn(y);
    const float rx = x - __half2float(hx), ry = y - __half2float(hy);
    const __half2 hi2 = __halves2half2(hx, hy);
    const __half2 lo2 = __halves2half2(__float2half_rn(rx), __float2half_rn(ry));
    lo = *(const uint32_t*)&lo2;
    return *(const uint32_t*)&hi2;
}

// ---------------- global scratch ----------------
__device__ __align__(128) unsigned char g_hh[100000 * 256];   // h hi fp16 [node][128]
__device__ __align__(128) unsigned char g_hl[100000 * 256];   // h lo-residual fp16
__device__ __align__(128) unsigned char g_w1t[4][16384];      // fp16 [slab][128n][64k] SW
__device__ __align__(128) unsigned char g_w2t[2][12288];      // fp16 [slab][96n][64k]  SW
__device__ int g_idx64;

__global__ void detect_idx_kernel(const unsigned long long* __restrict__ src) {
    if (threadIdx.x == 0) {
        int is64 = 1;
#pragma unroll
        for (int i = 0; i < 16; ++i)
            if ((src[i] >> 32) != 0ull) is64 = 0;
        g_idx64 = is64;
    }
}

__global__ void prep_w_kernel(const float* __restrict__ W1, const float* __restrict__ W2) {
    int i = blockIdx.x * blockDim.x + threadIdx.x;
    if (i < 128 * 256) {                     // W1T: n=0..127, k=0..255
        int n = i >> 8, k = i & 255;
        int slab = k >> 6, kk = k & 63;
        *(__half*)(g_w1t[slab] + SWZ(n * 128 + kk * 2)) = __float2half_rn(W1[k * DD + n]);
    } else if (i < 128 * 256 + 96 * 128) {   // W2T: n=0..95 (pad zero), k=0..127
        int j = i - 128 * 256;
        int n = j >> 7, k = j & 127;
        float w = (n < CC) ? W2[k * CC + n] : 0.0f;
        int slab = k >> 6, kk = k & 63;
        *(__half*)(g_w2t[slab] + SWZ(n * 128 + kk * 2)) = __float2half_rn(w);
    }
}

__global__ void prep_h_kernel(const float* __restrict__ h) {
    int i = blockIdx.x * blockDim.x + threadIdx.x;   // over 100000*128
    if (i < 100000 * 128) {
        float v = h[i];
        __half hv = __float2half_rn(v);
        __half lv = __float2half_rn(v - __half2float(hv));
        *(__half*)(g_hh + (size_t)i * 2) = hv;
        *(__half*)(g_hl + (size_t)i * 2) = lv;
    }
}

// ---------------- staging: one K-slab (64 wide) of A(hi/lo) + W1 ----
__device__ __forceinline__ void issue_slab(uint32_t smb, int s, int buf,
                                           const int* rows, int t) {
    const int koff2 = (s & 1) * 128;          // byte offset within 256B node row
    const uint32_t AHb = smb + BUF(buf) + OFF_AH;
    const uint32_t ALb = smb + BUF(buf) + OFF_AL;
    const uint32_t Wb  = smb + BUF(buf) + OFF_W;
#pragma unroll
    for (int r = 0; r < 2; ++r) {
        const int g = r * NT + t;             // 0..511 16B chunks
        const int e = g >> 3, q = g & 7;
        const size_t nb = (size_t)rows[e] * 256 + koff2 + q * 16;
        const uint32_t off = SWZ(e * 128 + q * 16);
        CP16(AHb + off, (const char*)g_hh + nb);
        CP16(ALb + off, (const char*)g_hl + nb);
    }
#pragma unroll
    for (int r = 0; r < 4; ++r) {
        const int g = r * NT + t;             // 0..1023 16B chunks
        CP16(Wb + g * 16, (const char*)g_w1t[s] + g * 16);
    }
}

// ---------------- main fused kernel ----------------
__global__ __launch_bounds__(NT, 2)
void mlp_mma_kernel(const float* __restrict__ b1g,
                    const float* __restrict__ b2g,
                    const void* __restrict__ srcp,
                    const void* __restrict__ dstp,
                    float* __restrict__ out)
{
    extern __shared__ char sm8[];
    const uint32_t smb = smem_u32(sm8);
    const int t = threadIdx.x;
    const int lane = t & 31;
    const int w = t >> 5;            // 0..7
    const int warp_m = w & 1;        // 32-row slice
    const int warp_n = w >> 1;       // layer1: 32-col slice; layer2: 24-col slice
    const long long e0 = (long long)blockIdx.x * BM;
    const int is64 = g_idx64;

    int* rs = (int*)(sm8 + SM_RS);
    int* rd = (int*)(sm8 + SM_RD);

    if (t < BM) {
        long long e = e0 + t;
        if (is64) { rs[t] = (int)((const long long*)srcp)[e]; rd[t] = (int)((const long long*)dstp)[e]; }
        else      { rs[t] = ((const int*)srcp)[e];            rd[t] = ((const int*)dstp)[e]; }
    }
    __syncthreads();

    // ===================== Layer 1 =====================
    float acc[2][4][4];
#pragma unroll
    for (int mt = 0; mt < 2; ++mt)
#pragma unroll
        for (int nt = 0; nt < 4; ++nt)
#pragma unroll
            for (int q = 0; q < 4; ++q) acc[mt][nt][q] = 0.0f;

    issue_slab(smb, 0, 0, rs, t);  CP_COMMIT();
    issue_slab(smb, 1, 1, rs, t);  CP_COMMIT();

    for (int s = 0; s < 4; ++s) {
        __syncthreads();                       // compute of slab s-1 done -> buf (s-1)%3 free
        if (s < 2) {
            issue_slab(smb, s + 2, (s + 2) % 3, rd, t);   // slabs 2,3 use dst rows
            CP_COMMIT();
        } else if (s == 2) {
            // stage W2 (single fp16, both K-slabs) into buf1 (slab1 done)
            const uint32_t W2b = smb + SM_W2;
#pragma unroll
            for (int r = 0; r < 6; ++r) {
                const int g = r * NT + t;      // 0..1535
                CP16(W2b + g * 16, (const char*)g_w2t[0] + g * 16);
            }
            CP_COMMIT();
        }
        if (s < 3) { CP_WAIT(2); } else { CP_WAIT(1); }   // slab s landed
        __syncthreads();

        const uint32_t AHb = smb + BUF(s % 3) + OFF_AH;
        const uint32_t ALb = smb + BUF(s % 3) + OFF_AL;
        const uint32_t Wb  = smb + BUF(s % 3) + OFF_W;
#pragma unroll
        for (int p = 0; p < 2; ++p) {          // A_hi x W, A_lo x W
            const uint32_t ab = p ? ALb : AHb;
#pragma unroll
            for (int ks = 0; ks < 4; ++ks) {
                const int k0 = ks * 16;
                uint32_t a[2][4];
#pragma unroll
                for (int mt = 0; mt < 2; ++mt) {
                    const int row = warp_m * 32 + mt * 16 + (lane & 15);
                    const int col = k0 + (lane >> 4) * 8;
                    ldsm4(a[mt], ab + SWZ(row * 128 + col * 2));
                }
#pragma unroll
                for (int nh = 0; nh < 2; ++nh) {
                    uint32_t b[4];
                    const int row = warp_n * 32 + nh * 16 + (lane & 7) + ((lane & 16) ? 8 : 0);
                    const int col = k0 + ((lane & 8) ? 8 : 0);
                    ldsm4(b, Wb + SWZ(row * 128 + col * 2));
                    mma16816(acc[0][nh * 2 + 0], a[0], b[0], b[1]);
                    mma16816(acc[0][nh * 2 + 1], a[0], b[2], b[3]);
                    mma16816(acc[1][nh * 2 + 0], a[1], b[0], b[1]);
                    mma16816(acc[1][nh * 2 + 1], a[1], b[2], b[3]);
                }
            }
        }
    }

    // ===================== Epilogue 1: bias+relu -> hid hi/lo (buf2) ========
    // All warps passed the s=3 barrier, so slab2 compute (buf2 reads) is done.
    {
        const int slab = warp_n >> 1;                 // cols 0..63 -> slab0; 64..127 -> slab1
        char* hh = sm8 + SM_HIDH + slab * 8192;
        char* hl = sm8 + SM_HIDL + slab * 8192;
#pragma unroll
        for (int mt = 0; mt < 2; ++mt) {
#pragma unroll
            for (int nt = 0; nt < 4; ++nt) {
                float* c = acc[mt][nt];
                const int n = warp_n * 32 + nt * 8 + 2 * (lane & 3);
                const float bl_ = __ldg(&b1g[n]), bh_ = __ldg(&b1g[n + 1]);
                float v00 = c[0] + bl_; v00 = v00 > 0.f ? v00 : 0.f;
                float v01 = c[1] + bh_; v01 = v01 > 0.f ? v01 : 0.f;
                float v10 = c[2] + bl_; v10 = v10 > 0.f ? v10 : 0.f;
                float v11 = c[3] + bh_; v11 = v11 > 0.f ? v11 : 0.f;
                uint32_t l0, l1;
                const uint32_t h0 = packsplit(v00, v01, l0);
                const uint32_t h1 = packsplit(v10, v11, l1);
                const int kk = (warp_n & 1) * 32 + nt * 8 + 2 * (lane & 3);  // 0..63 in slab
                const int row0 = warp_m * 32 + mt * 16 + (lane >> 2);
                const uint32_t oA = SWZ(row0 * 128 + kk * 2);
                const uint32_t oB = SWZ((row0 + 8) * 128 + kk * 2);
                *(uint32_t*)(hh + oA) = h0;  *(uint32_t*)(hl + oA) = l0;
                *(uint32_t*)(hh + oB) = h1;  *(uint32_t*)(hl + oB) = l1;
            }
        }
    }
    CP_WAIT(0);        // W2 landed
    __syncthreads();   // hid + W2 visible to all

    // ===================== Layer 2 =====================
    float acc2[2][3][4];
#pragma unroll
    for (int mt = 0; mt < 2; ++mt)
#pragma unroll
        for (int nt = 0; nt < 3; ++nt)
#pragma unroll
            for (int q = 0; q < 4; ++q) acc2[mt][nt][q] = 0.0f;

#pragma unroll
    for (int p = 0; p < 2; ++p) {              // hid_hi x W2, hid_lo x W2
        const uint32_t abase = smb + (p ? SM_HIDL : SM_HIDH);
#pragma unroll
        for (int ks = 0; ks < 8; ++ks) {
            const int kslab = ks >> 2;
            const int k0 = (ks & 3) * 16;
            const uint32_t ab = abase + kslab * 8192;
            const uint32_t bb = smb + SM_W2 + kslab * 12288;
            uint32_t a[2][4];
#pragma unroll
            for (int mt = 0; mt < 2; ++mt) {
                const int row = warp_m * 32 + mt * 16 + (lane & 15);
                const int col = k0 + (lane >> 4) * 8;
                ldsm4(a[mt], ab + SWZ(row * 128 + col * 2));
            }
#pragma unroll
            for (int nt2 = 0; nt2 < 3; ++nt2) {
                uint32_t b[2];
                const int row = warp_n * 24 + nt2 * 8 + (lane & 7);
                const int col = k0 + ((lane & 8) ? 8 : 0);
                ldsm2(b, bb + SWZ(row * 128 + col * 2));
                mma16816(acc2[0][nt2], a[0], b[0], b[1]);
                mma16816(acc2[1][nt2], a[1], b[0], b[1]);
            }
        }
    }

    // ===================== Epilogue 2: bias -> direct gmem stores ===========
    {
#pragma unroll
        for (int mt = 0; mt < 2; ++mt) {
#pragma unroll
            for (int nt2 = 0; nt2 < 3; ++nt2) {
                float* c = acc2[mt][nt2];
                const int n = warp_n * 24 + nt2 * 8 + 2 * (lane & 3);
                if (n < CC) {      // n even, so (n, n+1) both < 86 when n <= 84
                    const float bl_ = __ldg(&b2g[n]), bh_ = __ldg(&b2g[n + 1]);
                    const int row0 = warp_m * 32 + mt * 16 + (lane >> 2);
                    const long long eA = e0 + row0;
                    *(float2*)(out + eA * CC + n)       = make_float2(c[0] + bl_, c[1] + bh_);
                    *(float2*)(out + (eA + 8) * CC + n) = make_float2(c[2] + bl_, c[3] + bh_);
                }
            }
        }
    }
}

extern "C" void kernel_launch(void* const* d_in, const int* in_sizes, int n_in,
                              void* d_out, int out_size) {
    const float* h  = (const float*)d_in[0];
    const float* W1 = (const float*)d_in[1];
    const float* b1 = (const float*)d_in[2];
    const float* W2 = (const float*)d_in[3];
    const float* b2 = (const float*)d_in[4];
    const void* src = d_in[5];
    const void* dst = d_in[6];
    float* out = (float*)d_out;
    (void)in_sizes; (void)n_in; (void)out_size;

    cudaFuncSetAttribute(mlp_mma_kernel,
                         cudaFuncAttributeMaxDynamicSharedMemorySize, SMEM_BYTES);

    detect_idx_kernel<<<1, 32>>>((const unsigned long long*)src);
    prep_w_kernel<<<(128 * 256 + 96 * 128 + 255) / 256, 256>>>(W1, W2);
    prep_h_kernel<<<(100000 * 128 + 255) / 256, 256>>>(h);
    mlp_mma_kernel<<<NTILES, NT, SMEM_BYTES>>>(b1, b2, src, dst, out);
}

// round 11
// speedup vs baseline: 5.9706x; 1.0126x over previous
#include <cuda_runtime.h>
#include <cuda_fp16.h>
#include <stdint.h>

#define NE      1000000
#define DD      128
#define CC      86
#define BM      64
#define NT      256
#define NTILES  (NE / BM)     // 15625
#define GRID    296           // 2 CTAs/SM x 148 SMs, persistent

// ---------------- smem layout (bytes) ----------------
// Ring of two 32KB buffers: AH(8K) | AL(8K) | W(16K)
#define BUFB(i)  ((i) * 32768)
#define OFF_AH   0
#define OFF_AL   8192
#define OFF_W    16384
#define SM_HID   65536        // hid single fp16: 2 kslabs x 8192 ([64e][64k] SW)
#define SM_W2    81920        // W2 fp16 resident: 2 kslabs x 12288 ([96n][64k] SW)
#define SM_RS    106496       // [2][64] int (double-buffered indices)
#define SM_RD    107008       // [2][64] int
#define SMEM_BYTES 107520

#define SWZ(x) ((x) ^ ((((uint32_t)(x)) >> 3) & 0x70))

// ---------------- ptx helpers ----------------
__device__ __forceinline__ uint32_t smem_u32(const void* p) {
    uint32_t a;
    asm("{ .reg .u64 t; cvta.to.shared.u64 t, %1; cvt.u32.u64 %0, t; }" : "=r"(a) : "l"(p));
    return a;
}
#define CP16(dst, src) \
    asm volatile("cp.async.cg.shared.global [%0], [%1], 16;" :: "r"(dst), "l"(src))
#define CP_COMMIT() asm volatile("cp.async.commit_group;" ::: "memory")
#define CP_WAIT(n)  asm volatile("cp.async.wait_group %0;" :: "n"(n) : "memory")

__device__ __forceinline__ void ldsm4(uint32_t r[4], uint32_t addr) {
    asm volatile("ldmatrix.sync.aligned.m8n8.x4.shared.b16 {%0,%1,%2,%3}, [%4];"
                 : "=r"(r[0]), "=r"(r[1]), "=r"(r[2]), "=r"(r[3]) : "r"(addr));
}
__device__ __forceinline__ void ldsm2(uint32_t r[2], uint32_t addr) {
    asm volatile("ldmatrix.sync.aligned.m8n8.x2.shared.b16 {%0,%1}, [%2];"
                 : "=r"(r[0]), "=r"(r[1]) : "r"(addr));
}
__device__ __forceinline__ void mma16816(float c[4], const uint32_t a[4],
                                         uint32_t b0, uint32_t b1) {
    asm volatile("mma.sync.aligned.m16n8k16.row.col.f32.f16.f16.f32 "
                 "{%0,%1,%2,%3}, {%4,%5,%6,%7}, {%8,%9}, {%0,%1,%2,%3};"
                 : "+f"(c[0]), "+f"(c[1]), "+f"(c[2]), "+f"(c[3])
                 : "r"(a[0]), "r"(a[1]), "r"(a[2]), "r"(a[3]), "r"(b0), "r"(b1));
}
__device__ __forceinline__ uint32_t packh2(float x, float y) {
    const __half2 h2 = __halves2half2(__float2half_rn(x), __float2half_rn(y));
    return *(const uint32_t*)&h2;
}

// ---------------- global scratch ----------------
__device__ __align__(128) unsigned char g_hh[100000 * 256];   // h hi fp16 [node][128]
__device__ __align__(128) unsigned char g_hl[100000 * 256];   // h lo-residual fp16
__device__ __align__(128) unsigned char g_w1t[4][16384];      // fp16 [slab][128n][64k] SW
__device__ __align__(128) unsigned char g_w2t[2][12288];      // fp16 [slab][96n][64k]  SW
__device__ int g_idx64;

__global__ void detect_idx_kernel(const unsigned long long* __restrict__ src) {
    if (threadIdx.x == 0) {
        int is64 = 1;
#pragma unroll
        for (int i = 0; i < 16; ++i)
            if ((src[i] >> 32) != 0ull) is64 = 0;
        g_idx64 = is64;
    }
}

__global__ void prep_w_kernel(const float* __restrict__ W1, const float* __restrict__ W2) {
    int i = blockIdx.x * blockDim.x + threadIdx.x;
    if (i < 128 * 256) {                     // W1T: n=0..127, k=0..255
        int n = i >> 8, k = i & 255;
        int slab = k >> 6, kk = k & 63;
        *(__half*)(g_w1t[slab] + SWZ(n * 128 + kk * 2)) = __float2half_rn(W1[k * DD + n]);
    } else if (i < 128 * 256 + 96 * 128) {   // W2T: n=0..95 (pad zero), k=0..127
        int j = i - 128 * 256;
        int n = j >> 7, k = j & 127;
        float w = (n < CC) ? W2[k * CC + n] : 0.0f;
        int slab = k >> 6, kk = k & 63;
        *(__half*)(g_w2t[slab] + SWZ(n * 128 + kk * 2)) = __float2half_rn(w);
    }
}

__global__ void prep_h_kernel(const float* __restrict__ h) {
    int i = blockIdx.x * blockDim.x + threadIdx.x;   // over 100000*128
    if (i < 100000 * 128) {
        float v = h[i];
        __half hv = __float2half_rn(v);
        __half lv = __float2half_rn(v - __half2float(hv));
        *(__half*)(g_hh + (size_t)i * 2) = hv;
        *(__half*)(g_hl + (size_t)i * 2) = lv;
    }
}

// ---------------- staging: K-slab (64 wide) of A(hi/lo) + W1[wslab] --------
// wslab 0..3: buf = wslab&1, node k-offset = (wslab&1)*128 bytes
__device__ __forceinline__ void issue_slab(uint32_t smb, int wslab,
                                           const int* rows, int t) {
    const int koff2 = (wslab & 1) * 128;
    const uint32_t base = smb + BUFB(wslab & 1);
#pragma unroll
    for (int r = 0; r < 2; ++r) {
        const int g = r * NT + t;             // 0..511 16B chunks
        const int e = g >> 3, q = g & 7;
        const size_t nb = (size_t)rows[e] * 256 + koff2 + q * 16;
        const uint32_t off = SWZ(e * 128 + q * 16);
        CP16(base + OFF_AH + off, (const char*)g_hh + nb);
        CP16(base + OFF_AL + off, (const char*)g_hl + nb);
    }
#pragma unroll
    for (int r = 0; r < 4; ++r) {
        const int g = r * NT + t;             // 0..1023 16B chunks
        CP16(base + OFF_W + g * 16, (const char*)g_w1t[wslab] + g * 16);
    }
}

// ---------------- main persistent kernel ----------------
__global__ __launch_bounds__(NT, 2)
void mlp_mma_kernel(const float* __restrict__ b1g,
                    const float* __restrict__ b2g,
                    const void* __restrict__ srcp,
                    const void* __restrict__ dstp,
                    float* __restrict__ out)
{
    extern __shared__ char sm8[];
    const uint32_t smb = smem_u32(sm8);
    const int t = threadIdx.x;
    const int lane = t & 31;
    const int w = t >> 5;            // 0..7
    const int warp_m = w & 1;        // 32-row slice
    const int warp_n = w >> 1;       // layer1: 32-col slice; layer2: 24-col slice
    const int is64 = g_idx64;

    // ---- stage W2 once ----
    {
        const uint32_t W2b = smb + SM_W2;
#pragma unroll
        for (int r = 0; r < 6; ++r) {
            const int g = r * NT + t;          // 0..1535 chunks = 24576B
            CP16(W2b + g * 16, (const char*)g_w2t[0] + g * 16);
        }
        CP_COMMIT();
    }

    int tile = blockIdx.x;
    // ---- tile0 indices ----
    {
        int* rs0 = (int*)(sm8 + SM_RS);
        int* rd0 = (int*)(sm8 + SM_RD);
        if (t < 64) {
            long long e = (long long)tile * BM + t;
            rs0[t] = is64 ? (int)((const long long*)srcp)[e] : ((const int*)srcp)[e];
        } else if (t < 128) {
            long long e = (long long)tile * BM + (t - 64);
            rd0[t - 64] = is64 ? (int)((const long long*)dstp)[e] : ((const int*)dstp)[e];
        }
    }
    __syncthreads();
    issue_slab(smb, 0, (int*)(sm8 + SM_RS), t);  CP_COMMIT();
    issue_slab(smb, 1, (int*)(sm8 + SM_RS), t);  CP_COMMIT();

    int par = 0;
    for (; tile < NTILES; tile += GRID, par ^= 1) {
        const long long e0 = (long long)tile * BM;
        int* rdc = (int*)(sm8 + SM_RD) + par * 64;
        int* rsn = (int*)(sm8 + SM_RS) + (par ^ 1) * 64;
        int* rdn = (int*)(sm8 + SM_RD) + (par ^ 1) * 64;

        // prefetch next tile's indices (visible by the s=0 barrier)
        {
            int ntile = tile + GRID;
            if (ntile >= NTILES) ntile = tile;
            if (t < 64) {
                long long e = (long long)ntile * BM + t;
                rsn[t] = is64 ? (int)((const long long*)srcp)[e] : ((const int*)srcp)[e];
            } else if (t < 128) {
                long long e = (long long)ntile * BM + (t - 64);
                rdn[t - 64] = is64 ? (int)((const long long*)dstp)[e] : ((const int*)dstp)[e];
            }
        }

        // ===================== Layer 1 =====================
        float acc[2][4][4];
#pragma unroll
        for (int mt = 0; mt < 2; ++mt)
#pragma unroll
            for (int nt = 0; nt < 4; ++nt)
#pragma unroll
                for (int q = 0; q < 4; ++q) acc[mt][nt][q] = 0.0f;

#pragma unroll
        for (int s = 0; s < 4; ++s) {
            CP_WAIT(1);                        // slab s landed (1 newer outstanding)
            __syncthreads();

            const uint32_t base = smb + BUFB(s & 1);
            const uint32_t AHb = base + OFF_AH;
            const uint32_t ALb = base + OFF_AL;
            const uint32_t Wb  = base + OFF_W;
#pragma unroll
            for (int p = 0; p < 2; ++p) {      // A_hi x W, A_lo x W
                const uint32_t ab = p ? ALb : AHb;
#pragma unroll
                for (int ks = 0; ks < 4; ++ks) {
                    const int k0 = ks * 16;
                    uint32_t a[2][4];
#pragma unroll
                    for (int mt = 0; mt < 2; ++mt) {
                        const int row = warp_m * 32 + mt * 16 + (lane & 15);
                        const int col = k0 + (lane >> 4) * 8;
                        ldsm4(a[mt], ab + SWZ(row * 128 + col * 2));
                    }
#pragma unroll
                    for (int nh = 0; nh < 2; ++nh) {
                        uint32_t b[4];
                        const int row = warp_n * 32 + nh * 16 + (lane & 7) + ((lane & 16) ? 8 : 0);
                        const int col = k0 + ((lane & 8) ? 8 : 0);
                        ldsm4(b, Wb + SWZ(row * 128 + col * 2));
                        mma16816(acc[0][nh * 2 + 0], a[0], b[0], b[1]);
                        mma16816(acc[0][nh * 2 + 1], a[0], b[2], b[3]);
                        mma16816(acc[1][nh * 2 + 0], a[1], b[0], b[1]);
                        mma16816(acc[1][nh * 2 + 1], a[1], b[2], b[3]);
                    }
                }
            }
            __syncthreads();                   // buf s&1 free
            if (s < 2) issue_slab(smb, s + 2, rdc, t);       // this tile's dst slabs
            else       issue_slab(smb, s - 2, rsn, t);       // next tile's src slabs
            CP_COMMIT();
        }

        // ============ Epilogue 1: bias+relu -> hid (single fp16) ============
        {
            const int slab = warp_n >> 1;      // cols 0..63 -> kslab0; 64..127 -> kslab1
            char* hh = sm8 + SM_HID + slab * 8192;
#pragma unroll
            for (int mt = 0; mt < 2; ++mt) {
#pragma unroll
                for (int nt = 0; nt < 4; ++nt) {
                    float* c = acc[mt][nt];
                    const int n = warp_n * 32 + nt * 8 + 2 * (lane & 3);
                    const float bl_ = __ldg(&b1g[n]), bh_ = __ldg(&b1g[n + 1]);
                    float v00 = c[0] + bl_; v00 = v00 > 0.f ? v00 : 0.f;
                    float v01 = c[1] + bh_; v01 = v01 > 0.f ? v01 : 0.f;
                    float v10 = c[2] + bl_; v10 = v10 > 0.f ? v10 : 0.f;
                    float v11 = c[3] + bh_; v11 = v11 > 0.f ? v11 : 0.f;
                    const int kk = (warp_n & 1) * 32 + nt * 8 + 2 * (lane & 3);
                    const int row0 = warp_m * 32 + mt * 16 + (lane >> 2);
                    *(uint32_t*)(hh + SWZ(row0 * 128 + kk * 2))       = packh2(v00, v01);
                    *(uint32_t*)(hh + SWZ((row0 + 8) * 128 + kk * 2)) = packh2(v10, v11);
                }
            }
        }
        __syncthreads();   // hid visible to all

        // ===================== Layer 2 (1 pass) =====================
        float acc2[2][3][4];
#pragma unroll
        for (int mt = 0; mt < 2; ++mt)
#pragma unroll
            for (int nt = 0; nt < 3; ++nt)
#pragma unroll
                for (int q = 0; q < 4; ++q) acc2[mt][nt][q] = 0.0f;

#pragma unroll
        for (int ks = 0; ks < 8; ++ks) {
            const int kslab = ks >> 2;
            const int k0 = (ks & 3) * 16;
            const uint32_t ab = smb + SM_HID + kslab * 8192;
            const uint32_t bb = smb + SM_W2 + kslab * 12288;
            uint32_t a[2][4];
#pragma unroll
            for (int mt = 0; mt < 2; ++mt) {
                const int row = warp_m * 32 + mt * 16 + (lane & 15);
                const int col = k0 + (lane >> 4) * 8;
                ldsm4(a[mt], ab + SWZ(row * 128 + col * 2));
            }
#pragma unroll
            for (int nt2 = 0; nt2 < 3; ++nt2) {
                uint32_t b[2];
                const int row = warp_n * 24 + nt2 * 8 + (lane & 7);
                const int col = k0 + ((lane & 8) ? 8 : 0);
                ldsm2(b, bb + SWZ(row * 128 + col * 2));
                mma16816(acc2[0][nt2], a[0], b[0], b[1]);
                mma16816(acc2[1][nt2], a[1], b[0], b[1]);
            }
        }

        // ============ Epilogue 2: bias -> direct gmem stores ============
        {
#pragma unroll
            for (int mt = 0; mt < 2; ++mt) {
#pragma unroll
                for (int nt2 = 0; nt2 < 3; ++nt2) {
                    float* c = acc2[mt][nt2];
                    const int n = warp_n * 24 + nt2 * 8 + 2 * (lane & 3);
                    if (n < CC) {
                        const float bl_ = __ldg(&b2g[n]), bh_ = __ldg(&b2g[n + 1]);
                        const int row0 = warp_m * 32 + mt * 16 + (lane >> 2);
                        const long long eA = e0 + row0;
                        *(float2*)(out + eA * CC + n)       = make_float2(c[0] + bl_, c[1] + bh_);
                        *(float2*)(out + (eA + 8) * CC + n) = make_float2(c[2] + bl_, c[3] + bh_);
                    }
                }
            }
        }
    }
    CP_WAIT(0);    // drain ring before exit
}

extern "C" void kernel_launch(void* const* d_in, const int* in_sizes, int n_in,
                              void* d_out, int out_size) {
    const float* h  = (const float*)d_in[0];
    const float* W1 = (const float*)d_in[1];
    const float* b1 = (const float*)d_in[2];
    const float* W2 = (const float*)d_in[3];
    const float* b2 = (const float*)d_in[4];
    const void* src = d_in[5];
    const void* dst = d_in[6];
    float* out = (float*)d_out;
    (void)in_sizes; (void)n_in; (void)out_size;

    cudaFuncSetAttribute(mlp_mma_kernel,
                         cudaFuncAttributeMaxDynamicSharedMemorySize, SMEM_BYTES);

    detect_idx_kernel<<<1, 32>>>((const unsigned long long*)src);
    prep_w_kernel<<<(128 * 256 + 96 * 128 + 255) / 256, 256>>>(W1, W2);
    prep_h_kernel<<<(100000 * 128 + 255) / 256, 256>>>(h);
    mlp_mma_kernel<<<GRID, NT, SMEM_BYTES>>>(b1, b2, src, dst, out);
}

// round 14
// speedup vs baseline: 7.9755x; 1.3358x over previous
#include <cuda_runtime.h>
#include <cuda_fp16.h>
#include <stdint.h>

#define NE      1000000
#define DD      128
#define CC      86
#define BM      64
#define NT      256
#define NTILES  (NE / BM)     // 15625
#define GRID    296           // 2 CTAs/SM x 148 SMs, persistent

// ---------------- smem layout (bytes) ----------------
// Ring of two 24KB buffers: A(8K) | W(16K)
#define BUFB(i)  ((i) * 24576)
#define OFF_A    0
#define OFF_W    8192
#define SM_HID   49152        // hid fp16: 2 kslabs x 8192 ([64e][64k] SW)
#define SM_W2    65536        // W2 fp16 resident: 2 kslabs x 12288 ([96n][64k] SW)
#define SM_RS    90112        // [2][64] int (double-buffered indices)
#define SM_RD    90624        // [2][64] int
#define SMEM_BYTES 91136

#define SWZ(x) ((x) ^ ((((uint32_t)(x)) >> 3) & 0x70))

// ---------------- ptx helpers ----------------
__device__ __forceinline__ uint32_t smem_u32(const void* p) {
    uint32_t a;
    asm("{ .reg .u64 t; cvta.to.shared.u64 t, %1; cvt.u32.u64 %0, t; }" : "=r"(a) : "l"(p));
    return a;
}
#define CP16(dst, src) \
    asm volatile("cp.async.cg.shared.global [%0], [%1], 16;" :: "r"(dst), "l"(src))
#define CP_COMMIT() asm volatile("cp.async.commit_group;" ::: "memory")
#define CP_WAIT(n)  asm volatile("cp.async.wait_group %0;" :: "n"(n) : "memory")

__device__ __forceinline__ void ldsm4(uint32_t r[4], uint32_t addr) {
    asm volatile("ldmatrix.sync.aligned.m8n8.x4.shared.b16 {%0,%1,%2,%3}, [%4];"
                 : "=r"(r[0]), "=r"(r[1]), "=r"(r[2]), "=r"(r[3]) : "r"(addr));
}
__device__ __forceinline__ void ldsm2(uint32_t r[2], uint32_t addr) {
    asm volatile("ldmatrix.sync.aligned.m8n8.x2.shared.b16 {%0,%1}, [%2];"
                 : "=r"(r[0]), "=r"(r[1]) : "r"(addr));
}
__device__ __forceinline__ void mma16816(float c[4], const uint32_t a[4],
                                         uint32_t b0, uint32_t b1) {
    asm volatile("mma.sync.aligned.m16n8k16.row.col.f32.f16.f16.f32 "
                 "{%0,%1,%2,%3}, {%4,%5,%6,%7}, {%8,%9}, {%0,%1,%2,%3};"
                 : "+f"(c[0]), "+f"(c[1]), "+f"(c[2]), "+f"(c[3])
                 : "r"(a[0]), "r"(a[1]), "r"(a[2]), "r"(a[3]), "r"(b0), "r"(b1));
}
__device__ __forceinline__ uint32_t packh2(float x, float y) {
    const __half2 h2 = __halves2half2(__float2half_rn(x), __float2half_rn(y));
    return *(const uint32_t*)&h2;
}

// ---------------- global scratch ----------------
__device__ __align__(128) unsigned char g_hh[100000 * 256];   // h fp16 [node][128]
__device__ __align__(128) unsigned char g_w1t[4][16384];      // fp16 [slab][128n][64k] SW
__device__ __align__(128) unsigned char g_w2t[2][12288];      // fp16 [slab][96n][64k]  SW
__device__ int g_idx64;

__global__ void detect_idx_kernel(const unsigned long long* __restrict__ src) {
    if (threadIdx.x == 0) {
        int is64 = 1;
#pragma unroll
        for (int i = 0; i < 16; ++i)
            if ((src[i] >> 32) != 0ull) is64 = 0;
        g_idx64 = is64;
    }
}

__global__ void prep_w_kernel(const float* __restrict__ W1, const float* __restrict__ W2) {
    int i = blockIdx.x * blockDim.x + threadIdx.x;
    if (i < 128 * 256) {                     // W1T: n=0..127, k=0..255
        int n = i >> 8, k = i & 255;
        int slab = k >> 6, kk = k & 63;
        *(__half*)(g_w1t[slab] + SWZ(n * 128 + kk * 2)) = __float2half_rn(W1[k * DD + n]);
    } else if (i < 128 * 256 + 96 * 128) {   // W2T: n=0..95 (pad zero), k=0..127
        int j = i - 128 * 256;
        int n = j >> 7, k = j & 127;
        float w = (n < CC) ? W2[k * CC + n] : 0.0f;
        int slab = k >> 6, kk = k & 63;
        *(__half*)(g_w2t[slab] + SWZ(n * 128 + kk * 2)) = __float2half_rn(w);
    }
}

__global__ void prep_h_kernel(const float* __restrict__ h) {
    int i = blockIdx.x * blockDim.x + threadIdx.x;   // over 100000*128
    if (i < 100000 * 128)
        *(__half*)(g_hh + (size_t)i * 2) = __float2half_rn(h[i]);
}

// ---------------- staging: K-slab (64 wide) of A + W1[wslab] --------
// wslab 0..3: buf = wslab&1, node k-offset = (wslab&1)*128 bytes
__device__ __forceinline__ void issue_slab(uint32_t smb, int wslab,
                                           const int* rows, int t) {
    const int koff2 = (wslab & 1) * 128;
    const uint32_t base = smb + BUFB(wslab & 1);
#pragma unroll
    for (int r = 0; r < 2; ++r) {
        const int gg = r * NT + t;                // 0..511 16B chunks (A tile)
        const int e = gg >> 3, q = gg & 7;
        const size_t nb = (size_t)rows[e] * 256 + koff2 + q * 16;
        CP16(base + OFF_A + SWZ(e * 128 + q * 16), (const char*)g_hh + nb);
    }
#pragma unroll
    for (int r = 0; r < 4; ++r) {
        const int gg = r * NT + t;                // 0..1023 16B chunks (W tile)
        CP16(base + OFF_W + gg * 16, (const char*)g_w1t[wslab] + gg * 16);
    }
}

// ---------------- main persistent kernel ----------------
__global__ __launch_bounds__(NT, 2)
void mlp_mma_kernel(const float* __restrict__ b1g,
                    const float* __restrict__ b2g,
                    const void* __restrict__ srcp,
                    const void* __restrict__ dstp,
                    float* __restrict__ out)
{
    extern __shared__ char sm8[];
    const uint32_t smb = smem_u32(sm8);
    const int t = threadIdx.x;
    const int lane = t & 31;
    const int w = t >> 5;            // 0..7
    const int warp_m = w & 1;        // 32-row slice
    const int warp_n = w >> 1;       // layer1: 32-col slice; layer2: 24-col slice
    const int is64 = g_idx64;

    // ---- stage W2 once ----
    {
        const uint32_t W2b = smb + SM_W2;
#pragma unroll
        for (int r = 0; r < 6; ++r) {
            const int g = r * NT + t;          // 0..1535 chunks = 24576B
            CP16(W2b + g * 16, (const char*)g_w2t[0] + g * 16);
        }
        CP_COMMIT();
    }

    int tile = blockIdx.x;
    // ---- tile0 indices ----
    {
        int* rs0 = (int*)(sm8 + SM_RS);
        int* rd0 = (int*)(sm8 + SM_RD);
        if (t < 64) {
            long long e = (long long)tile * BM + t;
            rs0[t] = is64 ? (int)((const long long*)srcp)[e] : ((const int*)srcp)[e];
        } else if (t < 128) {
            long long e = (long long)tile * BM + (t - 64);
            rd0[t - 64] = is64 ? (int)((const long long*)dstp)[e] : ((const int*)dstp)[e];
        }
    }
    __syncthreads();
    issue_slab(smb, 0, (int*)(sm8 + SM_RS), t);  CP_COMMIT();
    issue_slab(smb, 1, (int*)(sm8 + SM_RS), t);  CP_COMMIT();

    int par = 0;
    for (; tile < NTILES; tile += GRID, par ^= 1) {
        const long long e0 = (long long)tile * BM;
        int* rdc = (int*)(sm8 + SM_RD) + par * 64;
        int* rsn = (int*)(sm8 + SM_RS) + (par ^ 1) * 64;
        int* rdn = (int*)(sm8 + SM_RD) + (par ^ 1) * 64;

        // prefetch next tile's indices (visible by the s=2 barrier)
        {
            int ntile = tile + GRID;
            if (ntile >= NTILES) ntile = tile;
            if (t < 64) {
                long long e = (long long)ntile * BM + t;
                rsn[t] = is64 ? (int)((const long long*)srcp)[e] : ((const int*)srcp)[e];
            } else if (t < 128) {
                long long e = (long long)ntile * BM + (t - 64);
                rdn[t - 64] = is64 ? (int)((const long long*)dstp)[e] : ((const int*)dstp)[e];
            }
        }

        // ===================== Layer 1 (single fp16 pass) =====================
        float acc[2][4][4];
#pragma unroll
        for (int mt = 0; mt < 2; ++mt)
#pragma unroll
            for (int nt = 0; nt < 4; ++nt)
#pragma unroll
                for (int q = 0; q < 4; ++q) acc[mt][nt][q] = 0.0f;

#pragma unroll
        for (int s = 0; s < 4; ++s) {
            CP_WAIT(1);                        // slab s landed (1 newer outstanding)
            __syncthreads();

            const uint32_t base = smb + BUFB(s & 1);
            const uint32_t Ab = base + OFF_A;
            const uint32_t Wb = base + OFF_W;
#pragma unroll
            for (int ks = 0; ks < 4; ++ks) {
                const int k0 = ks * 16;
                uint32_t a[2][4];
#pragma unroll
                for (int mt = 0; mt < 2; ++mt) {
                    const int row = warp_m * 32 + mt * 16 + (lane & 15);
                    const int col = k0 + (lane >> 4) * 8;
                    ldsm4(a[mt], Ab + SWZ(row * 128 + col * 2));
                }
#pragma unroll
                for (int nh = 0; nh < 2; ++nh) {
                    uint32_t b[4];
                    const int row = warp_n * 32 + nh * 16 + (lane & 7) + ((lane & 16) ? 8 : 0);
                    const int col = k0 + ((lane & 8) ? 8 : 0);
                    ldsm4(b, Wb + SWZ(row * 128 + col * 2));
                    mma16816(acc[0][nh * 2 + 0], a[0], b[0], b[1]);
                    mma16816(acc[0][nh * 2 + 1], a[0], b[2], b[3]);
                    mma16816(acc[1][nh * 2 + 0], a[1], b[0], b[1]);
                    mma16816(acc[1][nh * 2 + 1], a[1], b[2], b[3]);
                }
            }
            __syncthreads();                   // buf s&1 free
            if (s < 2) issue_slab(smb, s + 2, rdc, t);       // this tile's dst slabs
            else       issue_slab(smb, s - 2, rsn, t);       // next tile's src slabs
            CP_COMMIT();
        }

        // ============ Epilogue 1: bias+relu -> hid (fp16) ============
        {
            const int slab = warp_n >> 1;      // cols 0..63 -> kslab0; 64..127 -> kslab1
            char* hh = sm8 + SM_HID + slab * 8192;
#pragma unroll
            for (int mt = 0; mt < 2; ++mt) {
#pragma unroll
                for (int nt = 0; nt < 4; ++nt) {
                    float* c = acc[mt][nt];
                    const int n = warp_n * 32 + nt * 8 + 2 * (lane & 3);
                    const float bl_ = __ldg(&b1g[n]), bh_ = __ldg(&b1g[n + 1]);
                    float v00 = c[0] + bl_; v00 = v00 > 0.f ? v00 : 0.f;
                    float v01 = c[1] + bh_; v01 = v01 > 0.f ? v01 : 0.f;
                    float v10 = c[2] + bl_; v10 = v10 > 0.f ? v10 : 0.f;
                    float v11 = c[3] + bh_; v11 = v11 > 0.f ? v11 : 0.f;
                    const int kk = (warp_n & 1) * 32 + nt * 8 + 2 * (lane & 3);
                    const int row0 = warp_m * 32 + mt * 16 + (lane >> 2);
                    *(uint32_t*)(hh + SWZ(row0 * 128 + kk * 2))       = packh2(v00, v01);
                    *(uint32_t*)(hh + SWZ((row0 + 8) * 128 + kk * 2)) = packh2(v10, v11);
                }
            }
        }
        __syncthreads();   // hid visible to all

        // ===================== Layer 2 (1 pass) =====================
        float acc2[2][3][4];
#pragma unroll
        for (int mt = 0; mt < 2; ++mt)
#pragma unroll
            for (int nt = 0; nt < 3; ++nt)
#pragma unroll
                for (int q = 0; q < 4; ++q) acc2[mt][nt][q] = 0.0f;

#pragma unroll
        for (int ks = 0; ks < 8; ++ks) {
            const int kslab = ks >> 2;
            const int k0 = (ks & 3) * 16;
            const uint32_t ab = smb + SM_HID + kslab * 8192;
            const uint32_t bb = smb + SM_W2 + kslab * 12288;
            uint32_t a[2][4];
#pragma unroll
            for (int mt = 0; mt < 2; ++mt) {
                const int row = warp_m * 32 + mt * 16 + (lane & 15);
                const int col = k0 + (lane >> 4) * 8;
                ldsm4(a[mt], ab + SWZ(row * 128 + col * 2));
            }
#pragma unroll
            for (int nt2 = 0; nt2 < 3; ++nt2) {
                uint32_t b[2];
                const int row = warp_n * 24 + nt2 * 8 + (lane & 7);
                const int col = k0 + ((lane & 8) ? 8 : 0);
                ldsm2(b, bb + SWZ(row * 128 + col * 2));
                mma16816(acc2[0][nt2], a[0], b[0], b[1]);
                mma16816(acc2[1][nt2], a[1], b[0], b[1]);
            }
        }

        // ============ Epilogue 2: bias -> direct gmem stores ============
        {
#pragma unroll
            for (int mt = 0; mt < 2; ++mt) {
#pragma unroll
                for (int nt2 = 0; nt2 < 3; ++nt2) {
                    float* c = acc2[mt][nt2];
                    const int n = warp_n * 24 + nt2 * 8 + 2 * (lane & 3);
                    if (n < CC) {
                        const float bl_ = __ldg(&b2g[n]), bh_ = __ldg(&b2g[n + 1]);
                        const int row0 = warp_m * 32 + mt * 16 + (lane >> 2);
                        const long long eA = e0 + row0;
                        *(float2*)(out + eA * CC + n)       = make_float2(c[0] + bl_, c[1] + bh_);
                        *(float2*)(out + (eA + 8) * CC + n) = make_float2(c[2] + bl_, c[3] + bh_);
                    }
                }
            }
        }
    }
    CP_WAIT(0);    // drain ring before exit
}

extern "C" void kernel_launch(void* const* d_in, const int* in_sizes, int n_in,
                              void* d_out, int out_size) {
    const float* h  = (const float*)d_in[0];
    const float* W1 = (const float*)d_in[1];
    const float* b1 = (const float*)d_in[2];
    const float* W2 = (const float*)d_in[3];
    const float* b2 = (const float*)d_in[4];
    const void* src = d_in[5];
    const void* dst = d_in[6];
    float* out = (float*)d_out;
    (void)in_sizes; (void)n_in; (void)out_size;

    cudaFuncSetAttribute(mlp_mma_kernel,
                         cudaFuncAttributeMaxDynamicSharedMemorySize, SMEM_BYTES);

    detect_idx_kernel<<<1, 32>>>((const unsigned long long*)src);
    prep_w_kernel<<<(128 * 256 + 96 * 128 + 255) / 256, 256>>>(W1, W2);
    prep_h_kernel<<<(100000 * 128 + 255) / 256, 256>>>(h);
    mlp_mma_kernel<<<GRID, NT, SMEM_BYTES>>>(b1, b2, src, dst, out);
}

// round 15
// speedup vs baseline: 8.2016x; 1.0283x over previous
#include <cuda_runtime.h>
#include <cuda_fp16.h>
#include <stdint.h>

#define NE      1000000
#define DD      128
#define CC      86
#define BM      256
#define NT      512
#define NTILES  ((NE + BM - 1) / BM)   // 3907 (last tile: 64 valid edges)

// ---------------- smem layout (bytes) ----------------
#define SM_W1    0                      // resident W1: 4 kslabs x 16384 ([128n][64k] SW)
#define SM_W2    65536                  // resident W2: 2 kslabs x 12288 ([96n][64k] SW)
#define SM_A(i)  (90112 + (i) * 32768)  // A ring: 2 x [256e][64k] fp16 SW
#define SM_HID   155648                 // hid: 2 kslabs x 32768 ([256e][64k] SW)
#define SM_RS    221184                 // [2][256] int (double-buffered indices)
#define SM_RD    223232                 // [2][256] int
#define SMEM_BYTES 225280

#define SWZ(x) ((x) ^ ((((uint32_t)(x)) >> 3) & 0x70))

// ---------------- ptx helpers ----------------
__device__ __forceinline__ uint32_t smem_u32(const void* p) {
    uint32_t a;
    asm("{ .reg .u64 t; cvta.to.shared.u64 t, %1; cvt.u32.u64 %0, t; }" : "=r"(a) : "l"(p));
    return a;
}
#define CP16(dst, src) \
    asm volatile("cp.async.cg.shared.global [%0], [%1], 16;" :: "r"(dst), "l"(src))
#define CP_COMMIT() asm volatile("cp.async.commit_group;" ::: "memory")
#define CP_WAIT(n)  asm volatile("cp.async.wait_group %0;" :: "n"(n) : "memory")

__device__ __forceinline__ void ldsm4(uint32_t r[4], uint32_t addr) {
    asm volatile("ldmatrix.sync.aligned.m8n8.x4.shared.b16 {%0,%1,%2,%3}, [%4];"
                 : "=r"(r[0]), "=r"(r[1]), "=r"(r[2]), "=r"(r[3]) : "r"(addr));
}
__device__ __forceinline__ void mma16816(float c[4], const uint32_t a[4],
                                         uint32_t b0, uint32_t b1) {
    asm volatile("mma.sync.aligned.m16n8k16.row.col.f32.f16.f16.f32 "
                 "{%0,%1,%2,%3}, {%4,%5,%6,%7}, {%8,%9}, {%0,%1,%2,%3};"
                 : "+f"(c[0]), "+f"(c[1]), "+f"(c[2]), "+f"(c[3])
                 : "r"(a[0]), "r"(a[1]), "r"(a[2]), "r"(a[3]), "r"(b0), "r"(b1));
}
__device__ __forceinline__ uint32_t packh2(float x, float y) {
    const __half2 h2 = __halves2half2(__float2half_rn(x), __float2half_rn(y));
    return *(const uint32_t*)&h2;
}

// ---------------- global scratch ----------------
__device__ __align__(128) unsigned char g_hh[100000 * 256];   // h fp16 [node][128]
__device__ __align__(128) unsigned char g_w1t[4][16384];      // fp16 [kslab][128n][64k] SW
__device__ __align__(128) unsigned char g_w2t[2][12288];      // fp16 [kslab][96n][64k]  SW
__device__ int g_idx64;

// Merged prep: W transpose/convert + idx dtype detect
__global__ void prep_w_kernel(const float* __restrict__ W1, const float* __restrict__ W2,
                              const unsigned long long* __restrict__ src) {
    int i = blockIdx.x * blockDim.x + threadIdx.x;
    if (i == 0) {
        int is64 = 1;
#pragma unroll
        for (int k = 0; k < 16; ++k)
            if ((src[k] >> 32) != 0ull) is64 = 0;
        g_idx64 = is64;
    }
    if (i < 128 * 256) {                     // W1T: n=0..127, k=0..255
        int n = i >> 8, k = i & 255;
        int slab = k >> 6, kk = k & 63;
        *(__half*)(g_w1t[slab] + SWZ(n * 128 + kk * 2)) = __float2half_rn(W1[k * DD + n]);
    } else if (i < 128 * 256 + 96 * 128) {   // W2T: n=0..95 (pad zero), k=0..127
        int j = i - 128 * 256;
        int n = j >> 7, k = j & 127;
        float w = (n < CC) ? W2[k * CC + n] : 0.0f;
        int slab = k >> 6, kk = k & 63;
        *(__half*)(g_w2t[slab] + SWZ(n * 128 + kk * 2)) = __float2half_rn(w);
    }
}

__global__ void prep_h_kernel(const float* __restrict__ h) {
    int i = blockIdx.x * blockDim.x + threadIdx.x;
    if (i < 100000 * 128)
        *(__half*)(g_hh + (size_t)i * 2) = __float2half_rn(h[i]);
}

// ---------------- staging: one A K-slab (64 wide, 256 edges) ----------------
// wslab 0..3: buf = wslab&1, node k-byte-offset = (wslab&1)*128
__device__ __forceinline__ void issue_slabA(uint32_t smb, int wslab,
                                            const int* rows, int t) {
    const int koff2 = (wslab & 1) * 128;
    const uint32_t base = smb + SM_A(wslab & 1);
#pragma unroll
    for (int r = 0; r < 4; ++r) {
        const int gg = r * NT + t;            // 0..2047 16B chunks
        const int e = gg >> 3, q = gg & 7;
        const size_t nb = (size_t)rows[e] * 256 + koff2 + q * 16;
        CP16(base + SWZ(e * 128 + q * 16), (const char*)g_hh + nb);
    }
}

// ---------------- main persistent kernel (1 CTA/SM) ----------------
__global__ __launch_bounds__(NT, 1)
void mlp_mma_kernel(const float* __restrict__ b1g,
                    const float* __restrict__ b2g,
                    const void* __restrict__ srcp,
                    const void* __restrict__ dstp,
                    float* __restrict__ out)
{
    extern __shared__ char sm8[];
    const uint32_t smb = smem_u32(sm8);
    const int t = threadIdx.x;
    const int lane = t & 31;
    const int w = t >> 5;            // 0..15
    const int warp_m = w & 7;        // 32-row slice (of 256)
    const int warp_n = w >> 3;       // layer1: 64-col slice; layer2: 48-col slice
    const int is64 = g_idx64;
    const int stride = gridDim.x;

    // ---- stage resident W1 (64KB) + W2 (24KB) once: group G0 ----
#pragma unroll
    for (int r = 0; r < 8; ++r) {
        const int g = r * NT + t;             // 0..4095
        CP16(smb + SM_W1 + g * 16, (const char*)g_w1t[0] + g * 16);
    }
#pragma unroll
    for (int r = 0; r < 3; ++r) {
        const int g = r * NT + t;             // 0..1535
        CP16(smb + SM_W2 + g * 16, (const char*)g_w2t[0] + g * 16);
    }
    CP_COMMIT();

    int tile = blockIdx.x;
    if (tile >= NTILES) { CP_WAIT(0); return; }

    // ---- tile0 indices ----
    {
        int* rs0 = (int*)(sm8 + SM_RS);
        int* rd0 = (int*)(sm8 + SM_RD);
        long long e = (long long)tile * BM + (t & 255);
        if (e >= NE) e = NE - 1;
        if (t < 256) rs0[t]       = is64 ? (int)((const long long*)srcp)[e] : ((const int*)srcp)[e];
        else         rd0[t - 256] = is64 ? (int)((const long long*)dstp)[e] : ((const int*)dstp)[e];
    }
    __syncthreads();
    issue_slabA(smb, 0, (int*)(sm8 + SM_RS), t);  CP_COMMIT();   // G1
    issue_slabA(smb, 1, (int*)(sm8 + SM_RS), t);  CP_COMMIT();   // G2

    int par = 0;
    for (; tile < NTILES; tile += stride, par ^= 1) {
        const long long e0 = (long long)tile * BM;
        int* rdc = (int*)(sm8 + SM_RD) + par * 256;
        int* rsn = (int*)(sm8 + SM_RS) + (par ^ 1) * 256;
        int* rdn = (int*)(sm8 + SM_RD) + (par ^ 1) * 256;

        // prefetch next tile's indices (consumed at s>=2 after barriers)
        {
            int ntile = tile + stride;
            if (ntile >= NTILES) ntile = tile;
            long long e = (long long)ntile * BM + (t & 255);
            if (e >= NE) e = NE - 1;
            if (t < 256) rsn[t]       = is64 ? (int)((const long long*)srcp)[e] : ((const int*)srcp)[e];
            else         rdn[t - 256] = is64 ? (int)((const long long*)dstp)[e] : ((const int*)dstp)[e];
        }

        // ===================== Layer 1 =====================
        float acc[2][8][4];
#pragma unroll
        for (int mt = 0; mt < 2; ++mt)
#pragma unroll
            for (int nt = 0; nt < 8; ++nt)
#pragma unroll
                for (int q = 0; q < 4; ++q) acc[mt][nt][q] = 0.0f;

#pragma unroll
        for (int s = 0; s < 4; ++s) {
            CP_WAIT(1);                        // slab s (and W on s=0) landed
            __syncthreads();

            const uint32_t Ab = smb + SM_A(s & 1);
            const uint32_t Wb = smb + SM_W1 + s * 16384;
#pragma unroll
            for (int ks = 0; ks < 4; ++ks) {
                const int k0 = ks * 16;
                uint32_t a[2][4];
#pragma unroll
                for (int mt = 0; mt < 2; ++mt) {
                    const int row = warp_m * 32 + mt * 16 + (lane & 15);
                    const int col = k0 + (lane >> 4) * 8;
                    ldsm4(a[mt], Ab + SWZ(row * 128 + col * 2));
                }
#pragma unroll
                for (int nh = 0; nh < 4; ++nh) {
                    uint32_t b[4];
                    const int row = warp_n * 64 + nh * 16 + (lane & 7) + ((lane & 16) ? 8 : 0);
                    const int col = k0 + ((lane & 8) ? 8 : 0);
                    ldsm4(b, Wb + SWZ(row * 128 + col * 2));
                    mma16816(acc[0][nh * 2 + 0], a[0], b[0], b[1]);
                    mma16816(acc[0][nh * 2 + 1], a[0], b[2], b[3]);
                    mma16816(acc[1][nh * 2 + 0], a[1], b[0], b[1]);
                    mma16816(acc[1][nh * 2 + 1], a[1], b[2], b[3]);
                }
            }
            __syncthreads();                   // A buf s&1 free
            if (s < 2) issue_slabA(smb, s + 2, rdc, t);      // this tile's dst slabs
            else       issue_slabA(smb, s - 2, rsn, t);      // next tile's src slabs
            CP_COMMIT();
        }

        // ============ Epilogue 1: bias+relu -> hid (fp16) ============
        {
            char* hh = sm8 + SM_HID + warp_n * 32768;        // kslab = warp_n
#pragma unroll
            for (int mt = 0; mt < 2; ++mt) {
#pragma unroll
                for (int nt = 0; nt < 8; ++nt) {
                    float* c = acc[mt][nt];
                    const int n = warp_n * 64 + nt * 8 + 2 * (lane & 3);
                    const float bl_ = __ldg(&b1g[n]), bh_ = __ldg(&b1g[n + 1]);
                    float v00 = c[0] + bl_; v00 = v00 > 0.f ? v00 : 0.f;
                    float v01 = c[1] + bh_; v01 = v01 > 0.f ? v01 : 0.f;
                    float v10 = c[2] + bl_; v10 = v10 > 0.f ? v10 : 0.f;
                    float v11 = c[3] + bh_; v11 = v11 > 0.f ? v11 : 0.f;
                    const int kk = nt * 8 + 2 * (lane & 3);  // 0..63 within kslab
                    const int row0 = warp_m * 32 + mt * 16 + (lane >> 2);
                    *(uint32_t*)(hh + SWZ(row0 * 128 + kk * 2))       = packh2(v00, v01);
                    *(uint32_t*)(hh + SWZ((row0 + 8) * 128 + kk * 2)) = packh2(v10, v11);
                }
            }
        }
        __syncthreads();   // hid visible to all

        // ===================== Layer 2 =====================
        float acc2[2][6][4];
#pragma unroll
        for (int mt = 0; mt < 2; ++mt)
#pragma unroll
            for (int nt = 0; nt < 6; ++nt)
#pragma unroll
                for (int q = 0; q < 4; ++q) acc2[mt][nt][q] = 0.0f;

#pragma unroll
        for (int ks = 0; ks < 8; ++ks) {
            const int kslab = ks >> 2;
            const int k0 = (ks & 3) * 16;
            const uint32_t ab = smb + SM_HID + kslab * 32768;
            const uint32_t bb = smb + SM_W2 + kslab * 12288;
            uint32_t a[2][4];
#pragma unroll
            for (int mt = 0; mt < 2; ++mt) {
                const int row = warp_m * 32 + mt * 16 + (lane & 15);
                const int col = k0 + (lane >> 4) * 8;
                ldsm4(a[mt], ab + SWZ(row * 128 + col * 2));
            }
#pragma unroll
            for (int ng = 0; ng < 3; ++ng) {
                uint32_t b[4];
                const int row = warp_n * 48 + ng * 16 + (lane & 7) + ((lane & 16) ? 8 : 0);
                const int col = k0 + ((lane & 8) ? 8 : 0);
                ldsm4(b, bb + SWZ(row * 128 + col * 2));
                mma16816(acc2[0][ng * 2 + 0], a[0], b[0], b[1]);
                mma16816(acc2[0][ng * 2 + 1], a[0], b[2], b[3]);
                mma16816(acc2[1][ng * 2 + 0], a[1], b[0], b[1]);
                mma16816(acc2[1][ng * 2 + 1], a[1], b[2], b[3]);
            }
        }

        // ============ Epilogue 2: bias -> guarded gmem stores ============
        {
#pragma unroll
            for (int mt = 0; mt < 2; ++mt) {
#pragma unroll
                for (int nt2 = 0; nt2 < 6; ++nt2) {
                    float* c = acc2[mt][nt2];
                    const int n = warp_n * 48 + nt2 * 8 + 2 * (lane & 3);
                    if (n < CC) {      // n even -> (n, n+1) both valid when n <= 84
                        const float bl_ = __ldg(&b2g[n]), bh_ = __ldg(&b2g[n + 1]);
                        const int row0 = warp_m * 32 + mt * 16 + (lane >> 2);
                        const long long eA = e0 + row0;
                        const long long eB = eA + 8;
                        if (eA < NE)
                            *(float2*)(out + eA * CC + n) = make_float2(c[0] + bl_, c[1] + bh_);
                        if (eB < NE)
                            *(float2*)(out + eB * CC + n) = make_float2(c[2] + bl_, c[3] + bh_);
                    }
                }
            }
        }
    }
    CP_WAIT(0);    // drain ring before exit
}

extern "C" void kernel_launch(void* const* d_in, const int* in_sizes, int n_in,
                              void* d_out, int out_size) {
    const float* h  = (const float*)d_in[0];
    const float* W1 = (const float*)d_in[1];
    const float* b1 = (const float*)d_in[2];
    const float* W2 = (const float*)d_in[3];
    const float* b2 = (const float*)d_in[4];
    const void* src = d_in[5];
    const void* dst = d_in[6];
    float* out = (float*)d_out;
    (void)in_sizes; (void)n_in; (void)out_size;

    int dev = 0, nsm = 148;
    cudaGetDevice(&dev);
    cudaDeviceGetAttribute(&nsm, cudaDevAttrMultiProcessorCount, dev);

    cudaFuncSetAttribute(mlp_mma_kernel,
                         cudaFuncAttributeMaxDynamicSharedMemorySize, SMEM_BYTES);

    prep_w_kernel<<<(128 * 256 + 96 * 128 + 255) / 256, 256>>>(
        W1, W2, (const unsigned long long*)src);
    prep_h_kernel<<<(100000 * 128 + 255) / 256, 256>>>(h);
    mlp_mma_kernel<<<nsm, NT, SMEM_BYTES>>>(b1, b2, src, dst, out);
}